// round 5
// baseline (speedup 1.0000x reference)
#include <cuda_runtime.h>
#include <cstdint>

#define BB 2
#define SS 4096
#define DD 768
#define HH 12
#define HDD 64

// Scratch (device globals: no allocations allowed in kernel_launch)
__device__ float g_qkv[3*BB*SS*DD];   // q | k | v, contiguous
__device__ float g_ctx[BB*SS*DD];
__device__ float g_xr[BB*SS*DD];      // tf32-rounded x
__device__ float g_wr[4*DD*DD];       // tf32-rounded wq,wk,wv,wo

__device__ __forceinline__ uint32_t f2tf32(float x) {
    uint32_t u;
    asm("cvt.rna.tf32.f32 %0, %1;" : "=r"(u) : "f"(x));
    return u;
}
__device__ __forceinline__ float rtf(float x) { return __uint_as_float(f2tf32(x)); }

__device__ __forceinline__ void mma_tf32(
    float& d0, float& d1, float& d2, float& d3,
    uint32_t a0, uint32_t a1, uint32_t a2, uint32_t a3,
    uint32_t b0, uint32_t b1)
{
    asm volatile(
        "mma.sync.aligned.m16n8k8.row.col.f32.tf32.tf32.f32 "
        "{%0,%1,%2,%3}, {%4,%5,%6,%7}, {%8,%9}, {%0,%1,%2,%3};\n"
        : "+f"(d0), "+f"(d1), "+f"(d2), "+f"(d3)
        : "r"(a0), "r"(a1), "r"(a2), "r"(a3), "r"(b0), "r"(b1));
}

__device__ __forceinline__ void cpa16(void* dst, const void* src) {
    uint32_t d = (uint32_t)__cvta_generic_to_shared(dst);
    asm volatile("cp.async.ca.shared.global [%0], [%1], 16;\n" :: "r"(d), "l"(src));
}
#define CP_COMMIT asm volatile("cp.async.commit_group;\n" ::: "memory")
#define CP_WAIT0  asm volatile("cp.async.wait_group 0;\n" ::: "memory")

// ---------------------------------------------------------------------------
// fused tf32 rounding: blockIdx.y selects x / wq / wk / wv / wo
// ---------------------------------------------------------------------------
__global__ void round_all(const float4* __restrict__ x,
                          const float4* __restrict__ wq, const float4* __restrict__ wk,
                          const float4* __restrict__ wv, const float4* __restrict__ wo,
                          float4* __restrict__ xr, float4* __restrict__ wr)
{
    const int nx4 = BB*SS*DD/4, nw4 = DD*DD/4;
    const int z = blockIdx.y;
    const float4* src; float4* dst; int n4;
    if (z == 0) { src = x; dst = xr; n4 = nx4; }
    else {
        src = (z == 1) ? wq : (z == 2) ? wk : (z == 3) ? wv : wo;
        dst = wr + (size_t)(z-1) * nw4;
        n4 = nw4;
    }
    int i = blockIdx.x * blockDim.x + threadIdx.x;
    if (i < n4) {
        float4 v = src[i];
        dst[i] = make_float4(rtf(v.x), rtf(v.y), rtf(v.z), rtf(v.w));
    }
}

// ---------------------------------------------------------------------------
// tf32 GEMM: C[M,N] = A[M,K] @ W[N,K]^T (+bias). CTA 128x128, BK=32,
// 8 warps (2x4) of 64x32. 2-stage cp.async pipeline. Inputs pre-rounded tf32.
// blockIdx.z selects weight slice (z*DD*DD) and output slice (z*BB*SS*DD).
// SMEM row stride 36 (mod 32 = 4): scalar frag LDS.32 banks = 4g+tig, clean.
// ---------------------------------------------------------------------------
#define GLD 36
#define GSTG (128*GLD)

__global__ __launch_bounds__(256) void gemm_tf32(
    const float* __restrict__ A, const float* __restrict__ Wbase,
    const float* __restrict__ bias, float* __restrict__ Cbase,
    int round_out)
{
    extern __shared__ float gsm[];
    float* As = gsm;             // 2 stages x 128 x GLD
    float* Ws = gsm + 2*GSTG;

    const int K = DD, N = DD;
    const float* W = Wbase + (size_t)blockIdx.z * DD*DD;
    float* C = Cbase + (size_t)blockIdx.z * BB*SS*DD;

    const int tid  = threadIdx.x;
    const int lane = tid & 31;
    const int warp = tid >> 5;
    const int g = lane >> 2, tig = lane & 3;
    const int wm = warp & 1;
    const int wn = warp >> 1;
    const int bm = blockIdx.y * 128;
    const int bn = blockIdx.x * 128;

    float acc[4][4][4];
#pragma unroll
    for (int mi = 0; mi < 4; mi++)
#pragma unroll
        for (int ni = 0; ni < 4; ni++)
#pragma unroll
            for (int c = 0; c < 4; c++) acc[mi][ni][c] = 0.f;

    const int nk = K / 32;

    {
#pragma unroll
        for (int i = 0; i < 4; i++) {
            const int id = tid + 256*i;
            const int r = id >> 3;
            const int c = (id & 7) << 2;
            cpa16(&As[r*GLD + c], A + (size_t)(bm + r)*K + c);
            cpa16(&Ws[r*GLD + c], W + (size_t)(bn + r)*K + c);
        }
        CP_COMMIT;
    }

    for (int it = 0; it < nk; it++) {
        CP_WAIT0;
        __syncthreads();
        const int s = it & 1;
        if (it + 1 < nk) {
            const int k1 = (it + 1) * 32;
            float* Ad = As + (s^1)*GSTG;
            float* Wd = Ws + (s^1)*GSTG;
#pragma unroll
            for (int i = 0; i < 4; i++) {
                const int id = tid + 256*i;
                const int r = id >> 3;
                const int c = (id & 7) << 2;
                cpa16(&Ad[r*GLD + c], A + (size_t)(bm + r)*K + k1 + c);
                cpa16(&Wd[r*GLD + c], W + (size_t)(bn + r)*K + k1 + c);
            }
            CP_COMMIT;
        }
        const float* Ab = As + s*GSTG;
        const float* Wb = Ws + s*GSTG;
#pragma unroll
        for (int kk = 0; kk < 4; kk++) {
            uint32_t b0[4], b1[4];
#pragma unroll
            for (int ni = 0; ni < 4; ni++) {
                const float* wp = Wb + (32*wn + 8*ni + g)*GLD + 8*kk + tig;
                b0[ni] = __float_as_uint(wp[0]);
                b1[ni] = __float_as_uint(wp[4]);
            }
#pragma unroll
            for (int mi = 0; mi < 4; mi++) {
                const int rb = 64*wm + 16*mi;
                const float* ap0 = Ab + (rb + g)*GLD + 8*kk + tig;
                const float* ap1 = Ab + (rb + g + 8)*GLD + 8*kk + tig;
                const uint32_t a0 = __float_as_uint(ap0[0]);
                const uint32_t a1 = __float_as_uint(ap1[0]);
                const uint32_t a2 = __float_as_uint(ap0[4]);
                const uint32_t a3 = __float_as_uint(ap1[4]);
#pragma unroll
                for (int ni = 0; ni < 4; ni++)
                    mma_tf32(acc[mi][ni][0], acc[mi][ni][1],
                             acc[mi][ni][2], acc[mi][ni][3],
                             a0, a1, a2, a3, b0[ni], b1[ni]);
            }
        }
    }

#pragma unroll
    for (int ni = 0; ni < 4; ni++) {
        const int col = bn + 32*wn + 8*ni + 2*tig;
        float bx = 0.f, by = 0.f;
        if (bias) { bx = bias[col]; by = bias[col+1]; }
#pragma unroll
        for (int mi = 0; mi < 4; mi++) {
            const int r0 = bm + 64*wm + 16*mi + g;
            float v0 = acc[mi][ni][0] + bx, v1 = acc[mi][ni][1] + by;
            float v2 = acc[mi][ni][2] + bx, v3 = acc[mi][ni][3] + by;
            if (round_out) {   // q/k/v stored tf32-rounded: attn mma stays exact
                v0 = rtf(v0); v1 = rtf(v1); v2 = rtf(v2); v3 = rtf(v3);
            }
            *(float2*)(C + (size_t)r0*N + col)     = make_float2(v0, v1);
            *(float2*)(C + (size_t)(r0+8)*N + col) = make_float2(v2, v3);
        }
    }
}

// ---------------------------------------------------------------------------
// Flash attention, tf32 mma.sync. 8 warps (16-row bands), BQ=128, BK=64.
// K/V double-buffered via cp.async; P stays in registers (shfl re-layout).
// Strides: Q/K 68 (banks 4g+tig), V 72 (banks 8tig+g) — conflict-free LDS.32.
// 2 CTAs/SM (launch_bounds (256,2)) -> 16 warps/SM for softmax/mma overlap.
// ---------------------------------------------------------------------------
#define KLD 68
#define VLD 72

__global__ __launch_bounds__(256, 2) void attn_mma()
{
    extern __shared__ float smm[];
    float* Qs  = smm;                       // 128 x KLD
    float* Ksb = smm + 128*KLD;             // 2 x 64 x KLD
    float* Vsb = Ksb + 2*64*KLD;            // 2 x 64 x VLD

    const int tid  = threadIdx.x;
    const int lane = tid & 31;
    const int warp = tid >> 5;              // 0..7 -> 16-row band
    const int g = lane >> 2, tig = lane & 3;
    const int odd = tig & 1;
    const int bh = blockIdx.y;
    const int b  = bh / HH;
    const int h  = bh % HH;
    const int qt = (gridDim.x - 1) - blockIdx.x;   // heavy tiles first
    const int q0 = qt * 128;

    const float* Qg = g_qkv + 0*BB*SS*DD + ((size_t)b * SS) * DD + h * HDD;
    const float* Kg = g_qkv + 1*BB*SS*DD + ((size_t)b * SS) * DD + h * HDD;
    const float* Vg = g_qkv + 2*BB*SS*DD + ((size_t)b * SS) * DD + h * HDD;

    // prologue: Q tile + K/V tile 0 (256 threads)
    {
#pragma unroll
        for (int i = 0; i < 8; i++) {             // Q: 128 rows x 16 chunks
            const int id = tid + 256*i;
            const int r = id >> 4;
            const int c = (id & 15) << 2;
            cpa16(&Qs[r*KLD + c], Qg + (size_t)(q0 + r)*DD + c);
        }
#pragma unroll
        for (int i = 0; i < 4; i++) {             // K,V: 64 rows x 16 chunks
            const int id = tid + 256*i;
            const int r = id >> 4;
            const int c = (id & 15) << 2;
            cpa16(&Ksb[r*KLD + c], Kg + (size_t)r*DD + c);
            cpa16(&Vsb[r*VLD + c], Vg + (size_t)r*DD + c);
        }
        CP_COMMIT;
    }

    float s[8][4], o[8][4], mrow[2], lrow[2];
#pragma unroll
    for (int hi = 0; hi < 2; hi++) { mrow[hi] = -1e30f; lrow[hi] = 0.f; }
#pragma unroll
    for (int ni = 0; ni < 8; ni++)
#pragma unroll
        for (int c = 0; c < 4; c++) o[ni][c] = 0.f;

    const int rb = 16*warp;

    const int nkt = 2*qt + 2;
    for (int kt = 0; kt < nkt; kt++) {
        CP_WAIT0;
        __syncthreads();
        const int st = kt & 1;
        if (kt + 1 < nkt) {                      // prefetch next K/V tile
            const int k1 = (kt + 1) * 64;
            float* Kd = Ksb + (st^1)*64*KLD;
            float* Vd = Vsb + (st^1)*64*VLD;
#pragma unroll
            for (int i = 0; i < 4; i++) {
                const int id = tid + 256*i;
                const int r = id >> 4;
                const int c = (id & 15) << 2;
                cpa16(&Kd[r*KLD + c], Kg + (size_t)(k1 + r)*DD + c);
                cpa16(&Vd[r*VLD + c], Vg + (size_t)(k1 + r)*DD + c);
            }
            CP_COMMIT;
        }
        const float* Ks = Ksb + st*64*KLD;
        const float* Vs = Vsb + st*64*VLD;
        const int k0 = kt * 64;

        // ---- S = Q @ K^T (16 x 64 per warp) ----
#pragma unroll
        for (int ni = 0; ni < 8; ni++)
#pragma unroll
            for (int c = 0; c < 4; c++) s[ni][c] = 0.f;

#pragma unroll
        for (int kk = 0; kk < 8; kk++) {
            uint32_t b0[8], b1[8];
#pragma unroll
            for (int ni = 0; ni < 8; ni++) {
                const float* kp = Ks + (8*ni + g)*KLD + 8*kk + tig;
                b0[ni] = __float_as_uint(kp[0]);
                b1[ni] = __float_as_uint(kp[4]);
            }
            const float* qp0 = Qs + (rb + g)*KLD + 8*kk + tig;
            const float* qp1 = Qs + (rb + g + 8)*KLD + 8*kk + tig;
            const uint32_t a0 = __float_as_uint(qp0[0]);
            const uint32_t a1 = __float_as_uint(qp1[0]);
            const uint32_t a2 = __float_as_uint(qp0[4]);
            const uint32_t a3 = __float_as_uint(qp1[4]);
#pragma unroll
            for (int ni = 0; ni < 8; ni++)
                mma_tf32(s[ni][0], s[ni][1], s[ni][2], s[ni][3],
                         a0, a1, a2, a3, b0[ni], b1[ni]);
        }

        // ---- online softmax (4-lane groups share a row) ----
        const bool need_mask = (k0 + 63 > q0);
#pragma unroll
        for (int hi = 0; hi < 2; hi++) {
            const int row = q0 + rb + g + 8*hi;
            float mx = -1e30f;
#pragma unroll
            for (int ni = 0; ni < 8; ni++) {
#pragma unroll
                for (int cc = 0; cc < 2; cc++) {
                    float v = s[ni][2*hi+cc] * 0.125f;
                    if (need_mask && (k0 + 8*ni + 2*tig + cc > row)) v = -1e30f;
                    s[ni][2*hi+cc] = v;
                    mx = fmaxf(mx, v);
                }
            }
            mx = fmaxf(mx, __shfl_xor_sync(0xffffffffu, mx, 1));
            mx = fmaxf(mx, __shfl_xor_sync(0xffffffffu, mx, 2));
            const float mn = fmaxf(mrow[hi], mx);
            const float alpha = __expf(mrow[hi] - mn);
            mrow[hi] = mn;
            float rs = 0.f;
#pragma unroll
            for (int ni = 0; ni < 8; ni++) {
#pragma unroll
                for (int cc = 0; cc < 2; cc++) {
                    const float p = __expf(s[ni][2*hi+cc] - mn);
                    s[ni][2*hi+cc] = p;
                    rs += p;
                }
            }
            rs += __shfl_xor_sync(0xffffffffu, rs, 1);
            rs += __shfl_xor_sync(0xffffffffu, rs, 2);
            lrow[hi] = lrow[hi]*alpha + rs;
#pragma unroll
            for (int ni = 0; ni < 8; ni++) {
                o[ni][2*hi+0] *= alpha;
                o[ni][2*hi+1] *= alpha;
            }
        }

        // ---- O += P @ V; P fragments built in-register via shfl ----
        // S-output lane layout: row g cols (2tig,2tig+1). PV A-frag needs row g
        // cols (tig, tig+4): source lanes base+(tig>>1) and base+(tig>>1)+2,
        // register selected by tig&1.
#pragma unroll
        for (int kk = 0; kk < 8; kk++) {
            uint32_t b0[8], b1[8];
#pragma unroll
            for (int ni = 0; ni < 8; ni++) {
                b0[ni] = __float_as_uint(Vs[(8*kk + tig)*VLD + 8*ni + g]);
                b1[ni] = __float_as_uint(Vs[(8*kk + tig + 4)*VLD + 8*ni + g]);
            }
            const int srcA = (lane & ~3) | (tig >> 1);
            const int srcB = srcA + 2;
            const float v0 = __shfl_sync(0xffffffffu, s[kk][0], srcA);
            const float v1 = __shfl_sync(0xffffffffu, s[kk][1], srcA);
            const float v2 = __shfl_sync(0xffffffffu, s[kk][2], srcA);
            const float v3 = __shfl_sync(0xffffffffu, s[kk][3], srcA);
            const float w0 = __shfl_sync(0xffffffffu, s[kk][0], srcB);
            const float w1 = __shfl_sync(0xffffffffu, s[kk][1], srcB);
            const float w2 = __shfl_sync(0xffffffffu, s[kk][2], srcB);
            const float w3 = __shfl_sync(0xffffffffu, s[kk][3], srcB);
            const uint32_t pa0 = f2tf32(odd ? v1 : v0);
            const uint32_t pa1 = f2tf32(odd ? v3 : v2);
            const uint32_t pa2 = f2tf32(odd ? w1 : w0);
            const uint32_t pa3 = f2tf32(odd ? w3 : w2);
#pragma unroll
            for (int ni = 0; ni < 8; ni++)
                mma_tf32(o[ni][0], o[ni][1], o[ni][2], o[ni][3],
                         pa0, pa1, pa2, pa3, b0[ni], b1[ni]);
        }
    }

    // ---- normalize + write ctx [b, s, h, hd] (tf32-rounded for out-proj) ----
#pragma unroll
    for (int hi = 0; hi < 2; hi++) {
        const float inv = 1.f / lrow[hi];
        const int row = q0 + rb + g + 8*hi;
        float* dst = g_ctx + ((size_t)b * SS + row) * DD + h * HDD;
#pragma unroll
        for (int ni = 0; ni < 8; ni++) {
            *(float2*)(dst + 8*ni + 2*tig) =
                make_float2(rtf(o[ni][2*hi+0]*inv),
                            rtf(o[ni][2*hi+1]*inv));
        }
    }
}

// ---------------------------------------------------------------------------
extern "C" void kernel_launch(void* const* d_in, const int* in_sizes, int n_in,
                              void* d_out, int out_size)
{
    const float* x  = (const float*)d_in[0];
    const float* wq = (const float*)d_in[1];
    const float* wk = (const float*)d_in[2];
    const float* wv = (const float*)d_in[3];
    const float* wo = (const float*)d_in[4];
    const float* bo = (const float*)d_in[5];
    float* out = (float*)d_out;

    float *gqkv, *gctx, *gxr, *gwr;
    cudaGetSymbolAddress((void**)&gqkv, g_qkv);
    cudaGetSymbolAddress((void**)&gctx, g_ctx);
    cudaGetSymbolAddress((void**)&gxr,  g_xr);
    cudaGetSymbolAddress((void**)&gwr,  g_wr);

    const int gemm_smem = 4 * GSTG * (int)sizeof(float);        // 73728
    cudaFuncSetAttribute(gemm_tf32,
                         cudaFuncAttributeMaxDynamicSharedMemorySize, gemm_smem);
    const int attn_smem = (128*KLD + 2*64*KLD + 2*64*VLD) * (int)sizeof(float); // 106496
    cudaFuncSetAttribute(attn_mma,
                         cudaFuncAttributeMaxDynamicSharedMemorySize, attn_smem);

    // pre-round x + all 4 weights to tf32 (rna), one fused launch
    const int nx4 = BB*SS*DD/4;
    round_all<<<dim3((nx4+255)/256, 5), 256>>>(
        (const float4*)x, (const float4*)wq, (const float4*)wk,
        (const float4*)wv, (const float4*)wo, (float4*)gxr, (float4*)gwr);

    dim3 gblock(256);

    // fused QKV projection: z selects weight + output slice
    gemm_tf32<<<dim3(DD/128, (BB*SS)/128, 3), gblock, gemm_smem>>>(
        gxr, gwr, nullptr, gqkv, 1);

    attn_mma<<<dim3(SS/128, BB*HH), 256, attn_smem>>>();

    gemm_tf32<<<dim3(DD/128, (BB*SS)/128, 1), gblock, gemm_smem>>>(
        gctx, gwr + 3*DD*DD, bo, out, 0);
}

// round 6
// speedup vs baseline: 1.0483x; 1.0483x over previous
#include <cuda_runtime.h>
#include <cstdint>

#define BB 2
#define SS 4096
#define DD 768
#define HH 12
#define HDD 64

// Scratch (device globals: no allocations allowed in kernel_launch)
__device__ float g_qkv[3*BB*SS*DD];   // q | k | v, contiguous
__device__ float g_ctx[BB*SS*DD];
__device__ float g_xr[BB*SS*DD];      // tf32-rounded x
__device__ float g_wr[4*DD*DD];       // tf32-rounded wq,wk,wv,wo

__device__ __forceinline__ uint32_t f2tf32(float x) {
    uint32_t u;
    asm("cvt.rna.tf32.f32 %0, %1;" : "=r"(u) : "f"(x));
    return u;
}
__device__ __forceinline__ float rtf(float x) { return __uint_as_float(f2tf32(x)); }

__device__ __forceinline__ void mma_tf32(
    float& d0, float& d1, float& d2, float& d3,
    uint32_t a0, uint32_t a1, uint32_t a2, uint32_t a3,
    uint32_t b0, uint32_t b1)
{
    asm volatile(
        "mma.sync.aligned.m16n8k8.row.col.f32.tf32.tf32.f32 "
        "{%0,%1,%2,%3}, {%4,%5,%6,%7}, {%8,%9}, {%0,%1,%2,%3};\n"
        : "+f"(d0), "+f"(d1), "+f"(d2), "+f"(d3)
        : "r"(a0), "r"(a1), "r"(a2), "r"(a3), "r"(b0), "r"(b1));
}

__device__ __forceinline__ void cpa16(void* dst, const void* src) {
    uint32_t d = (uint32_t)__cvta_generic_to_shared(dst);
    asm volatile("cp.async.ca.shared.global [%0], [%1], 16;\n" :: "r"(d), "l"(src));
}
#define CP_COMMIT asm volatile("cp.async.commit_group;\n" ::: "memory")
#define CP_WAITN(n) asm volatile("cp.async.wait_group %0;\n" :: "n"(n) : "memory")
#define CP_WAIT0  CP_WAITN(0)

// ---------------------------------------------------------------------------
// fused tf32 rounding: blockIdx.y selects x / wq / wk / wv / wo
// ---------------------------------------------------------------------------
__global__ void round_all(const float4* __restrict__ x,
                          const float4* __restrict__ wq, const float4* __restrict__ wk,
                          const float4* __restrict__ wv, const float4* __restrict__ wo,
                          float4* __restrict__ xr, float4* __restrict__ wr)
{
    const int nx4 = BB*SS*DD/4, nw4 = DD*DD/4;
    const int z = blockIdx.y;
    const float4* src; float4* dst; int n4;
    if (z == 0) { src = x; dst = xr; n4 = nx4; }
    else {
        src = (z == 1) ? wq : (z == 2) ? wk : (z == 3) ? wv : wo;
        dst = wr + (size_t)(z-1) * nw4;
        n4 = nw4;
    }
    int i = blockIdx.x * blockDim.x + threadIdx.x;
    if (i < n4) {
        float4 v = src[i];
        dst[i] = make_float4(rtf(v.x), rtf(v.y), rtf(v.z), rtf(v.w));
    }
}

// ---------------------------------------------------------------------------
// tf32 GEMM: C[M,N] = A[M,K] @ W[N,K]^T (+bias). CTA 128x128, BK=32,
// 8 warps (2x4) of 64x32. 3-stage cp.async pipeline (wait_group 1 keeps one
// tile load in flight behind compute). Inputs pre-rounded tf32.
// blockIdx.z selects weight slice (z*DD*DD) and output slice (z*BB*SS*DD).
// SMEM row stride 36 (mod 32 = 4): scalar frag LDS.32 banks = 4g+tig, clean.
// ---------------------------------------------------------------------------
#define GLD 36
#define GSTG (128*GLD)
#define GNS  3

__global__ __launch_bounds__(256) void gemm_tf32(
    const float* __restrict__ A, const float* __restrict__ Wbase,
    const float* __restrict__ bias, float* __restrict__ Cbase,
    int round_out)
{
    extern __shared__ float gsm[];
    float* As = gsm;                 // GNS stages x 128 x GLD
    float* Ws = gsm + GNS*GSTG;

    const int K = DD, N = DD;
    const float* W = Wbase + (size_t)blockIdx.z * DD*DD;
    float* C = Cbase + (size_t)blockIdx.z * BB*SS*DD;

    const int tid  = threadIdx.x;
    const int lane = tid & 31;
    const int warp = tid >> 5;
    const int g = lane >> 2, tig = lane & 3;
    const int wm = warp & 1;
    const int wn = warp >> 1;
    const int bm = blockIdx.y * 128;
    const int bn = blockIdx.x * 128;

    float acc[4][4][4];
#pragma unroll
    for (int mi = 0; mi < 4; mi++)
#pragma unroll
        for (int ni = 0; ni < 4; ni++)
#pragma unroll
            for (int c = 0; c < 4; c++) acc[mi][ni][c] = 0.f;

    const int nk = K / 32;

    auto stage = [&](int t) {
        const int s = t % GNS;
        float* Ad = As + s*GSTG;
        float* Wd = Ws + s*GSTG;
        const int k0 = t * 32;
#pragma unroll
        for (int i = 0; i < 4; i++) {
            const int id = tid + 256*i;
            const int r = id >> 3;
            const int c = (id & 7) << 2;
            cpa16(&Ad[r*GLD + c], A + (size_t)(bm + r)*K + k0 + c);
            cpa16(&Wd[r*GLD + c], W + (size_t)(bn + r)*K + k0 + c);
        }
        CP_COMMIT;
    };

    stage(0);
    stage(1);

    for (int it = 0; it < nk; it++) {
        if (it + 1 < nk) CP_WAITN(1); else CP_WAIT0;
        __syncthreads();
        if (it + 2 < nk) stage(it + 2);
        const int s = it % GNS;
        const float* Ab = As + s*GSTG;
        const float* Wb = Ws + s*GSTG;
#pragma unroll
        for (int kk = 0; kk < 4; kk++) {
            uint32_t b0[4], b1[4];
#pragma unroll
            for (int ni = 0; ni < 4; ni++) {
                const float* wp = Wb + (32*wn + 8*ni + g)*GLD + 8*kk + tig;
                b0[ni] = __float_as_uint(wp[0]);
                b1[ni] = __float_as_uint(wp[4]);
            }
#pragma unroll
            for (int mi = 0; mi < 4; mi++) {
                const int rb = 64*wm + 16*mi;
                const float* ap0 = Ab + (rb + g)*GLD + 8*kk + tig;
                const float* ap1 = Ab + (rb + g + 8)*GLD + 8*kk + tig;
                const uint32_t a0 = __float_as_uint(ap0[0]);
                const uint32_t a1 = __float_as_uint(ap1[0]);
                const uint32_t a2 = __float_as_uint(ap0[4]);
                const uint32_t a3 = __float_as_uint(ap1[4]);
#pragma unroll
                for (int ni = 0; ni < 4; ni++)
                    mma_tf32(acc[mi][ni][0], acc[mi][ni][1],
                             acc[mi][ni][2], acc[mi][ni][3],
                             a0, a1, a2, a3, b0[ni], b1[ni]);
            }
        }
        __syncthreads();
    }

#pragma unroll
    for (int ni = 0; ni < 4; ni++) {
        const int col = bn + 32*wn + 8*ni + 2*tig;
        float bx = 0.f, by = 0.f;
        if (bias) { bx = bias[col]; by = bias[col+1]; }
#pragma unroll
        for (int mi = 0; mi < 4; mi++) {
            const int r0 = bm + 64*wm + 16*mi + g;
            float v0 = acc[mi][ni][0] + bx, v1 = acc[mi][ni][1] + by;
            float v2 = acc[mi][ni][2] + bx, v3 = acc[mi][ni][3] + by;
            if (round_out) {   // q/k/v stored tf32-rounded: attn mma stays exact
                v0 = rtf(v0); v1 = rtf(v1); v2 = rtf(v2); v3 = rtf(v3);
            }
            *(float2*)(C + (size_t)r0*N + col)     = make_float2(v0, v1);
            *(float2*)(C + (size_t)(r0+8)*N + col) = make_float2(v2, v3);
        }
    }
}

// ---------------------------------------------------------------------------
// Flash attention, tf32 mma.sync. 8 warps (16-row bands), BQ=128, BK=64.
// K/V double-buffered via cp.async. Q fragments hoisted to registers
// (pre-scaled by 1/8). PV consumes the S fragment DIRECTLY as an A-fragment:
// B k-slot j is bound to key 2j (j<4) / 2(j-4)+1 (j>=4) by loading V rows
// (8kk+2tig, 8kk+2tig+1) -> no shfl re-layout at all.
// Strides: Q/K/V all 68 -> conflict-free LDS.32 patterns.
// ---------------------------------------------------------------------------
#define KLD 68
#define VLD 68

__global__ __launch_bounds__(256, 2) void attn_mma()
{
    extern __shared__ float smm[];
    float* Qs  = smm;                       // 128 x KLD
    float* Ksb = smm + 128*KLD;             // 2 x 64 x KLD
    float* Vsb = Ksb + 2*64*KLD;            // 2 x 64 x VLD

    const int tid  = threadIdx.x;
    const int lane = tid & 31;
    const int warp = tid >> 5;              // 0..7 -> 16-row band
    const int g = lane >> 2, tig = lane & 3;
    const int bh = blockIdx.y;
    const int b  = bh / HH;
    const int h  = bh % HH;
    const int qt = (gridDim.x - 1) - blockIdx.x;   // heavy tiles first
    const int q0 = qt * 128;

    const float* Qg = g_qkv + 0*BB*SS*DD + ((size_t)b * SS) * DD + h * HDD;
    const float* Kg = g_qkv + 1*BB*SS*DD + ((size_t)b * SS) * DD + h * HDD;
    const float* Vg = g_qkv + 2*BB*SS*DD + ((size_t)b * SS) * DD + h * HDD;

    // prologue: Q tile + K/V tile 0 (256 threads)
    {
#pragma unroll
        for (int i = 0; i < 8; i++) {             // Q: 128 rows x 16 chunks
            const int id = tid + 256*i;
            const int r = id >> 4;
            const int c = (id & 15) << 2;
            cpa16(&Qs[r*KLD + c], Qg + (size_t)(q0 + r)*DD + c);
        }
#pragma unroll
        for (int i = 0; i < 4; i++) {             // K,V: 64 rows x 16 chunks
            const int id = tid + 256*i;
            const int r = id >> 4;
            const int c = (id & 15) << 2;
            cpa16(&Ksb[r*KLD + c], Kg + (size_t)r*DD + c);
            cpa16(&Vsb[r*VLD + c], Vg + (size_t)r*DD + c);
        }
        CP_COMMIT;
    }

    float qa[8][4];                 // hoisted Q fragments (pre-scaled by 1/8)
    float s[8][4], o[8][4], mrow[2], lrow[2];
#pragma unroll
    for (int hi = 0; hi < 2; hi++) { mrow[hi] = -1e30f; lrow[hi] = 0.f; }
#pragma unroll
    for (int ni = 0; ni < 8; ni++)
#pragma unroll
        for (int c = 0; c < 4; c++) o[ni][c] = 0.f;

    const int rb = 16*warp;

    const int nkt = 2*qt + 2;
    for (int kt = 0; kt < nkt; kt++) {
        CP_WAIT0;
        __syncthreads();
        const int st = kt & 1;
        if (kt + 1 < nkt) {                      // prefetch next K/V tile
            const int k1 = (kt + 1) * 64;
            float* Kd = Ksb + (st^1)*64*KLD;
            float* Vd = Vsb + (st^1)*64*VLD;
#pragma unroll
            for (int i = 0; i < 4; i++) {
                const int id = tid + 256*i;
                const int r = id >> 4;
                const int c = (id & 15) << 2;
                cpa16(&Kd[r*KLD + c], Kg + (size_t)(k1 + r)*DD + c);
                cpa16(&Vd[r*VLD + c], Vg + (size_t)(k1 + r)*DD + c);
            }
            CP_COMMIT;
        }
        if (kt == 0) {                           // hoist Q frags once
#pragma unroll
            for (int kk = 0; kk < 8; kk++) {
                qa[kk][0] = 0.125f * Qs[(rb + g)*KLD     + 8*kk + tig];
                qa[kk][1] = 0.125f * Qs[(rb + g + 8)*KLD + 8*kk + tig];
                qa[kk][2] = 0.125f * Qs[(rb + g)*KLD     + 8*kk + tig + 4];
                qa[kk][3] = 0.125f * Qs[(rb + g + 8)*KLD + 8*kk + tig + 4];
            }
        }
        const float* Ks = Ksb + st*64*KLD;
        const float* Vs = Vsb + st*64*VLD;
        const int k0 = kt * 64;

        // ---- S = (Q/8) @ K^T (16 x 64 per warp) ----
#pragma unroll
        for (int ni = 0; ni < 8; ni++)
#pragma unroll
            for (int c = 0; c < 4; c++) s[ni][c] = 0.f;

#pragma unroll
        for (int kk = 0; kk < 8; kk++) {
            uint32_t b0[8], b1[8];
#pragma unroll
            for (int ni = 0; ni < 8; ni++) {
                const float* kp = Ks + (8*ni + g)*KLD + 8*kk + tig;
                b0[ni] = __float_as_uint(kp[0]);
                b1[ni] = __float_as_uint(kp[4]);
            }
            const uint32_t a0 = __float_as_uint(qa[kk][0]);
            const uint32_t a1 = __float_as_uint(qa[kk][1]);
            const uint32_t a2 = __float_as_uint(qa[kk][2]);
            const uint32_t a3 = __float_as_uint(qa[kk][3]);
#pragma unroll
            for (int ni = 0; ni < 8; ni++)
                mma_tf32(s[ni][0], s[ni][1], s[ni][2], s[ni][3],
                         a0, a1, a2, a3, b0[ni], b1[ni]);
        }

        // ---- online softmax (scores already scaled; 4-lane groups = row) ----
        const bool need_mask = (k0 + 63 > q0);
#pragma unroll
        for (int hi = 0; hi < 2; hi++) {
            const int row = q0 + rb + g + 8*hi;
            float mx = -1e30f;
#pragma unroll
            for (int ni = 0; ni < 8; ni++) {
#pragma unroll
                for (int cc = 0; cc < 2; cc++) {
                    float v = s[ni][2*hi+cc];
                    if (need_mask && (k0 + 8*ni + 2*tig + cc > row)) v = -1e30f;
                    s[ni][2*hi+cc] = v;
                    mx = fmaxf(mx, v);
                }
            }
            mx = fmaxf(mx, __shfl_xor_sync(0xffffffffu, mx, 1));
            mx = fmaxf(mx, __shfl_xor_sync(0xffffffffu, mx, 2));
            const float mn = fmaxf(mrow[hi], mx);
            const float alpha = __expf(mrow[hi] - mn);
            mrow[hi] = mn;
            float rs = 0.f;
#pragma unroll
            for (int ni = 0; ni < 8; ni++) {
#pragma unroll
                for (int cc = 0; cc < 2; cc++) {
                    const float p = __expf(s[ni][2*hi+cc] - mn);
                    s[ni][2*hi+cc] = p;
                    rs += p;
                }
            }
            rs += __shfl_xor_sync(0xffffffffu, rs, 1);
            rs += __shfl_xor_sync(0xffffffffu, rs, 2);
            lrow[hi] = lrow[hi]*alpha + rs;
#pragma unroll
            for (int ni = 0; ni < 8; ni++) {
                o[ni][2*hi+0] *= alpha;
                o[ni][2*hi+1] *= alpha;
            }
        }

        // ---- O += P @ V, shfl-free: S frag used directly as A frag.
        // A k-slot j holds key 2j (j<4) / 2(j-4)+1 (j>=4); B rows bound to the
        // same keys: b0 from V row 8kk+2tig, b1 from V row 8kk+2tig+1. ----
#pragma unroll
        for (int kk = 0; kk < 8; kk++) {
            uint32_t b0[8], b1[8];
            const float* vp0 = Vs + (8*kk + 2*tig)*VLD + g;
#pragma unroll
            for (int ni = 0; ni < 8; ni++) {
                b0[ni] = __float_as_uint(vp0[8*ni]);
                b1[ni] = __float_as_uint(vp0[VLD + 8*ni]);
            }
            const uint32_t pa0 = f2tf32(s[kk][0]);
            const uint32_t pa1 = f2tf32(s[kk][2]);
            const uint32_t pa2 = f2tf32(s[kk][1]);
            const uint32_t pa3 = f2tf32(s[kk][3]);
#pragma unroll
            for (int ni = 0; ni < 8; ni++)
                mma_tf32(o[ni][0], o[ni][1], o[ni][2], o[ni][3],
                         pa0, pa1, pa2, pa3, b0[ni], b1[ni]);
        }
    }

    // ---- normalize + write ctx [b, s, h, hd] (tf32-rounded for out-proj) ----
#pragma unroll
    for (int hi = 0; hi < 2; hi++) {
        const float inv = 1.f / lrow[hi];
        const int row = q0 + rb + g + 8*hi;
        float* dst = g_ctx + ((size_t)b * SS + row) * DD + h * HDD;
#pragma unroll
        for (int ni = 0; ni < 8; ni++) {
            *(float2*)(dst + 8*ni + 2*tig) =
                make_float2(rtf(o[ni][2*hi+0]*inv),
                            rtf(o[ni][2*hi+1]*inv));
        }
    }
}

// ---------------------------------------------------------------------------
extern "C" void kernel_launch(void* const* d_in, const int* in_sizes, int n_in,
                              void* d_out, int out_size)
{
    const float* x  = (const float*)d_in[0];
    const float* wq = (const float*)d_in[1];
    const float* wk = (const float*)d_in[2];
    const float* wv = (const float*)d_in[3];
    const float* wo = (const float*)d_in[4];
    const float* bo = (const float*)d_in[5];
    float* out = (float*)d_out;

    float *gqkv, *gctx, *gxr, *gwr;
    cudaGetSymbolAddress((void**)&gqkv, g_qkv);
    cudaGetSymbolAddress((void**)&gctx, g_ctx);
    cudaGetSymbolAddress((void**)&gxr,  g_xr);
    cudaGetSymbolAddress((void**)&gwr,  g_wr);

    const int gemm_smem = 2 * GNS * GSTG * (int)sizeof(float);  // 110592
    cudaFuncSetAttribute(gemm_tf32,
                         cudaFuncAttributeMaxDynamicSharedMemorySize, gemm_smem);
    const int attn_smem = (128*KLD + 2*64*KLD + 2*64*VLD) * (int)sizeof(float); // 104448
    cudaFuncSetAttribute(attn_mma,
                         cudaFuncAttributeMaxDynamicSharedMemorySize, attn_smem);

    // pre-round x + all 4 weights to tf32 (rna), one fused launch
    const int nx4 = BB*SS*DD/4;
    round_all<<<dim3((nx4+255)/256, 5), 256>>>(
        (const float4*)x, (const float4*)wq, (const float4*)wk,
        (const float4*)wv, (const float4*)wo, (float4*)gxr, (float4*)gwr);

    dim3 gblock(256);

    // fused QKV projection: z selects weight + output slice
    gemm_tf32<<<dim3(DD/128, (BB*SS)/128, 3), gblock, gemm_smem>>>(
        gxr, gwr, nullptr, gqkv, 1);

    attn_mma<<<dim3(SS/128, BB*HH), 256, attn_smem>>>();

    gemm_tf32<<<dim3(DD/128, (BB*SS)/128, 1), gblock, gemm_smem>>>(
        gctx, gwr + 3*DD*DD, bo, out, 0);
}

// round 7
// speedup vs baseline: 1.0484x; 1.0001x over previous
#include <cuda_runtime.h>
#include <cstdint>

#define BB 2
#define SS 4096
#define DD 768
#define HH 12
#define HDD 64

// Scratch (device globals: no allocations allowed in kernel_launch)
__device__ float g_qkv[3*BB*SS*DD];   // q | k(col-pair-permuted) | v(row-pair-interleaved)
__device__ float g_ctx[BB*SS*DD];
__device__ float g_xr[BB*SS*DD];      // tf32-rounded x
__device__ float g_wr[4*DD*DD];       // tf32-rounded wq,wk,wv,wo

__device__ __forceinline__ uint32_t f2tf32(float x) {
    uint32_t u;
    asm("cvt.rna.tf32.f32 %0, %1;" : "=r"(u) : "f"(x));
    return u;
}
__device__ __forceinline__ float rtf(float x) { return __uint_as_float(f2tf32(x)); }

__device__ __forceinline__ void mma_tf32(
    float& d0, float& d1, float& d2, float& d3,
    uint32_t a0, uint32_t a1, uint32_t a2, uint32_t a3,
    uint32_t b0, uint32_t b1)
{
    asm volatile(
        "mma.sync.aligned.m16n8k8.row.col.f32.tf32.tf32.f32 "
        "{%0,%1,%2,%3}, {%4,%5,%6,%7}, {%8,%9}, {%0,%1,%2,%3};\n"
        : "+f"(d0), "+f"(d1), "+f"(d2), "+f"(d3)
        : "r"(a0), "r"(a1), "r"(a2), "r"(a3), "r"(b0), "r"(b1));
}

__device__ __forceinline__ void cpa16(void* dst, const void* src) {
    uint32_t d = (uint32_t)__cvta_generic_to_shared(dst);
    asm volatile("cp.async.ca.shared.global [%0], [%1], 16;\n" :: "r"(d), "l"(src));
}
#define CP_COMMIT asm volatile("cp.async.commit_group;\n" ::: "memory")
#define CP_WAITN(n) asm volatile("cp.async.wait_group %0;\n" :: "n"(n) : "memory")
#define CP_WAIT0  CP_WAITN(0)

// ---------------------------------------------------------------------------
// fused tf32 rounding: blockIdx.y selects x / wq / wk / wv / wo
// ---------------------------------------------------------------------------
__global__ void round_all(const float4* __restrict__ x,
                          const float4* __restrict__ wq, const float4* __restrict__ wk,
                          const float4* __restrict__ wv, const float4* __restrict__ wo,
                          float4* __restrict__ xr, float4* __restrict__ wr)
{
    const int nx4 = BB*SS*DD/4, nw4 = DD*DD/4;
    const int z = blockIdx.y;
    const float4* src; float4* dst; int n4;
    if (z == 0) { src = x; dst = xr; n4 = nx4; }
    else {
        src = (z == 1) ? wq : (z == 2) ? wk : (z == 3) ? wv : wo;
        dst = wr + (size_t)(z-1) * nw4;
        n4 = nw4;
    }
    int i = blockIdx.x * blockDim.x + threadIdx.x;
    if (i < n4) {
        float4 v = src[i];
        dst[i] = make_float4(rtf(v.x), rtf(v.y), rtf(v.z), rtf(v.w));
    }
}

// ---------------------------------------------------------------------------
// tf32 GEMM: C[M,N] = A[M,K] @ W[N,K]^T (+bias). CTA 128x128, BK=32,
// 8 warps (2x4) of 64x32. 3-stage cp.async pipeline, ONE barrier per K-iter.
// mode==0: plain fp32 output + bias (out-proj).
// mode==1: fused QKV (blockIdx.z = 0/1/2 -> Q/K/V), outputs tf32-rounded.
//   Q: plain layout.  K: column-pair-permuted within 8-groups.
//   V: row-pair-interleaved vil[b][s/2][h][2*hd + (s&1)].
// ---------------------------------------------------------------------------
#define GLD 36
#define GSTG (128*GLD)
#define GNS  3

__global__ __launch_bounds__(256) void gemm_tf32(
    const float* __restrict__ A, const float* __restrict__ Wbase,
    const float* __restrict__ bias, float* __restrict__ Cbase,
    int mode)
{
    extern __shared__ float gsm[];
    float* As = gsm;                 // GNS stages x 128 x GLD
    float* Ws = gsm + GNS*GSTG;

    const int K = DD, N = DD;
    const float* W = Wbase + (size_t)blockIdx.z * DD*DD;
    float* C = Cbase + (size_t)blockIdx.z * BB*SS*DD;

    const int tid  = threadIdx.x;
    const int lane = tid & 31;
    const int warp = tid >> 5;
    const int g = lane >> 2, tig = lane & 3;
    const int wm = warp & 1;
    const int wn = warp >> 1;
    const int bm = blockIdx.y * 128;
    const int bn = blockIdx.x * 128;

    float acc[4][4][4];
#pragma unroll
    for (int mi = 0; mi < 4; mi++)
#pragma unroll
        for (int ni = 0; ni < 4; ni++)
#pragma unroll
            for (int c = 0; c < 4; c++) acc[mi][ni][c] = 0.f;

    const int nk = K / 32;

    auto stage = [&](int t) {
        const int s = t % GNS;
        float* Ad = As + s*GSTG;
        float* Wd = Ws + s*GSTG;
        const int k0 = t * 32;
#pragma unroll
        for (int i = 0; i < 4; i++) {
            const int id = tid + 256*i;
            const int r = id >> 3;
            const int c = (id & 7) << 2;
            cpa16(&Ad[r*GLD + c], A + (size_t)(bm + r)*K + k0 + c);
            cpa16(&Wd[r*GLD + c], W + (size_t)(bn + r)*K + k0 + c);
        }
        CP_COMMIT;
    };

    stage(0);
    stage(1);

    for (int it = 0; it < nk; it++) {
        if (it + 1 < nk) CP_WAITN(1); else CP_WAIT0;
        __syncthreads();
        if (it + 2 < nk) stage(it + 2);
        const int s = it % GNS;
        const float* Ab = As + s*GSTG;
        const float* Wb = Ws + s*GSTG;
#pragma unroll
        for (int kk = 0; kk < 4; kk++) {
            uint32_t b0[4], b1[4];
#pragma unroll
            for (int ni = 0; ni < 4; ni++) {
                const float* wp = Wb + (32*wn + 8*ni + g)*GLD + 8*kk + tig;
                b0[ni] = __float_as_uint(wp[0]);
                b1[ni] = __float_as_uint(wp[4]);
            }
#pragma unroll
            for (int mi = 0; mi < 4; mi++) {
                const int rb = 64*wm + 16*mi;
                const float* ap0 = Ab + (rb + g)*GLD + 8*kk + tig;
                const float* ap1 = Ab + (rb + g + 8)*GLD + 8*kk + tig;
                const uint32_t a0 = __float_as_uint(ap0[0]);
                const uint32_t a1 = __float_as_uint(ap1[0]);
                const uint32_t a2 = __float_as_uint(ap0[4]);
                const uint32_t a3 = __float_as_uint(ap1[4]);
#pragma unroll
                for (int ni = 0; ni < 4; ni++)
                    mma_tf32(acc[mi][ni][0], acc[mi][ni][1],
                             acc[mi][ni][2], acc[mi][ni][3],
                             a0, a1, a2, a3, b0[ni], b1[ni]);
            }
        }
    }

    const int z = blockIdx.z;
#pragma unroll
    for (int ni = 0; ni < 4; ni++) {
        const int col = bn + 32*wn + 8*ni + 2*tig;
        float bx = 0.f, by = 0.f;
        if (mode == 0 && bias) { bx = bias[col]; by = bias[col+1]; }
#pragma unroll
        for (int mi = 0; mi < 4; mi++) {
            const int r0 = bm + 64*wm + 16*mi + g;
            float v0 = acc[mi][ni][0] + bx, v1 = acc[mi][ni][1] + by;
            float v2 = acc[mi][ni][2] + bx, v3 = acc[mi][ni][3] + by;
            if (mode == 0) {
                *(float2*)(C + (size_t)r0*N + col)     = make_float2(v0, v1);
                *(float2*)(C + (size_t)(r0+8)*N + col) = make_float2(v2, v3);
                continue;
            }
            v0 = rtf(v0); v1 = rtf(v1); v2 = rtf(v2); v3 = rtf(v3);
            if (z == 0) {                 // Q: plain
                *(float2*)(C + (size_t)r0*N + col)     = make_float2(v0, v1);
                *(float2*)(C + (size_t)(r0+8)*N + col) = make_float2(v2, v3);
            } else if (z == 1) {          // K: col-pair permuted within 8-group
                const int pc = (col & ~7) | ((col & 3) << 1) | ((col >> 2) & 1);
                C[(size_t)r0*N + pc]       = v0;   // perm(col)
                C[(size_t)r0*N + pc + 2]   = v1;   // perm(col+1) = pc+2
                C[(size_t)(r0+8)*N + pc]     = v2;
                C[(size_t)(r0+8)*N + pc + 2] = v3;
            } else {                      // V: row-pair interleaved
                const int h = col >> 6, hd = col & 63;
#pragma unroll
                for (int rr = 0; rr < 2; rr++) {
                    const int r = r0 + 8*rr;
                    const int b = r >> 12, sq = r & (SS-1);
                    float* vp = C + ((size_t)(b*(SS/2) + (sq>>1))*HH + h)*128
                                  + 2*hd + (sq & 1);
                    vp[0] = rr ? v2 : v0;
                    vp[2] = rr ? v3 : v1;
                }
            }
        }
    }
}

// ---------------------------------------------------------------------------
// Flash attention, tf32 mma.sync. 8 warps (16-row bands), BQ=128, BK=64.
// K/V double-buffered via cp.async. Q frags hoisted (pre-scaled by 1/8).
// K arrives col-pair-permuted  -> S-phase B-frag = one LDS.64.
// V arrives row-pair-interleaved -> PV B-frag = one LDS.64 (shfl-free PV).
// Strides: Q/K 72, V 136 (both ==8 mod 32) -> conflict-free 64-bit phases.
// ---------------------------------------------------------------------------
#define KLD 72
#define VLD2 136

__global__ __launch_bounds__(256, 2) void attn_mma()
{
    extern __shared__ float smm[];
    float* Qs  = smm;                        // 128 x KLD
    float* Ksb = smm + 128*KLD;              // 2 x 64 x KLD
    float* Vsb = Ksb + 2*64*KLD;             // 2 x 32 x VLD2

    const int tid  = threadIdx.x;
    const int lane = tid & 31;
    const int warp = tid >> 5;               // 0..7 -> 16-row band
    const int g = lane >> 2, tig = lane & 3;
    const int bh = blockIdx.y;
    const int b  = bh / HH;
    const int h  = bh % HH;
    const int qt = (gridDim.x - 1) - blockIdx.x;   // heavy tiles first
    const int q0 = qt * 128;

    const float* Qg = g_qkv + 0*BB*SS*DD + ((size_t)b * SS) * DD + h * HDD;
    const float* Kg = g_qkv + 1*BB*SS*DD + ((size_t)b * SS) * DD + h * HDD;
    // V interleaved: row p (key pair) at  vbase + p*(HH*128) + h*128
    const float* Vg = g_qkv + 2*BB*SS*DD + (size_t)b*(SS/2)*HH*128 + h*128;

    // prologue: Q tile + K/V tile 0
    {
#pragma unroll
        for (int i = 0; i < 8; i++) {             // Q: 128 rows x 16 chunks
            const int id = tid + 256*i;
            const int r = id >> 4;
            const int c = (id & 15) << 2;
            cpa16(&Qs[r*KLD + c], Qg + (size_t)(q0 + r)*DD + c);
        }
#pragma unroll
        for (int i = 0; i < 4; i++) {             // K: 64 rows x 16 chunks
            const int id = tid + 256*i;
            const int r = id >> 4;
            const int c = (id & 15) << 2;
            cpa16(&Ksb[r*KLD + c], Kg + (size_t)r*DD + c);
        }
#pragma unroll
        for (int i = 0; i < 4; i++) {             // V: 32 pair-rows x 32 chunks
            const int id = tid + 256*i;
            const int p = id >> 5;
            const int c = (id & 31) << 2;
            cpa16(&Vsb[p*VLD2 + c], Vg + (size_t)p*(HH*128) + c);
        }
        CP_COMMIT;
    }

    float qa[8][4];                 // hoisted Q fragments (pre-scaled by 1/8)
    float s[8][4], o[8][4], mrow[2], lrow[2];
#pragma unroll
    for (int hi = 0; hi < 2; hi++) { mrow[hi] = -1e30f; lrow[hi] = 0.f; }
#pragma unroll
    for (int ni = 0; ni < 8; ni++)
#pragma unroll
        for (int c = 0; c < 4; c++) o[ni][c] = 0.f;

    const int rb = 16*warp;

    const int nkt = 2*qt + 2;
    for (int kt = 0; kt < nkt; kt++) {
        CP_WAIT0;
        __syncthreads();
        const int st = kt & 1;
        if (kt + 1 < nkt) {                      // prefetch next K/V tile
            const int k1 = (kt + 1) * 64;
            float* Kd = Ksb + (st^1)*64*KLD;
            float* Vd = Vsb + (st^1)*32*VLD2;
#pragma unroll
            for (int i = 0; i < 4; i++) {
                const int id = tid + 256*i;
                const int r = id >> 4;
                const int c = (id & 15) << 2;
                cpa16(&Kd[r*KLD + c], Kg + (size_t)(k1 + r)*DD + c);
            }
#pragma unroll
            for (int i = 0; i < 4; i++) {
                const int id = tid + 256*i;
                const int p = id >> 5;
                const int c = (id & 31) << 2;
                cpa16(&Vd[p*VLD2 + c], Vg + (size_t)(k1/2 + p)*(HH*128) + c);
            }
            CP_COMMIT;
        }
        if (kt == 0) {                           // hoist Q frags once
#pragma unroll
            for (int kk = 0; kk < 8; kk++) {
                qa[kk][0] = 0.125f * Qs[(rb + g)*KLD     + 8*kk + tig];
                qa[kk][1] = 0.125f * Qs[(rb + g + 8)*KLD + 8*kk + tig];
                qa[kk][2] = 0.125f * Qs[(rb + g)*KLD     + 8*kk + tig + 4];
                qa[kk][3] = 0.125f * Qs[(rb + g + 8)*KLD + 8*kk + tig + 4];
            }
        }
        const float* Ks = Ksb + st*64*KLD;
        const float* Vs = Vsb + st*32*VLD2;
        const int k0 = kt * 64;

        // ---- S = (Q/8) @ K^T; K is col-pair-permuted: B-frag = LDS.64 ----
#pragma unroll
        for (int ni = 0; ni < 8; ni++)
#pragma unroll
            for (int c = 0; c < 4; c++) s[ni][c] = 0.f;

#pragma unroll
        for (int kk = 0; kk < 8; kk++) {
            uint32_t b0[8], b1[8];
#pragma unroll
            for (int ni = 0; ni < 8; ni++) {
                const float2 kb = *(const float2*)(Ks + (8*ni + g)*KLD + 8*kk + 2*tig);
                b0[ni] = __float_as_uint(kb.x);   // logical col 8kk+tig
                b1[ni] = __float_as_uint(kb.y);   // logical col 8kk+tig+4
            }
            const uint32_t a0 = __float_as_uint(qa[kk][0]);
            const uint32_t a1 = __float_as_uint(qa[kk][1]);
            const uint32_t a2 = __float_as_uint(qa[kk][2]);
            const uint32_t a3 = __float_as_uint(qa[kk][3]);
#pragma unroll
            for (int ni = 0; ni < 8; ni++)
                mma_tf32(s[ni][0], s[ni][1], s[ni][2], s[ni][3],
                         a0, a1, a2, a3, b0[ni], b1[ni]);
        }

        // ---- online softmax (scores pre-scaled; 4-lane groups = row) ----
        const bool need_mask = (k0 + 63 > q0);
#pragma unroll
        for (int hi = 0; hi < 2; hi++) {
            const int row = q0 + rb + g + 8*hi;
            float mx = -1e30f;
#pragma unroll
            for (int ni = 0; ni < 8; ni++) {
#pragma unroll
                for (int cc = 0; cc < 2; cc++) {
                    float v = s[ni][2*hi+cc];
                    if (need_mask && (k0 + 8*ni + 2*tig + cc > row)) v = -1e30f;
                    s[ni][2*hi+cc] = v;
                    mx = fmaxf(mx, v);
                }
            }
            mx = fmaxf(mx, __shfl_xor_sync(0xffffffffu, mx, 1));
            mx = fmaxf(mx, __shfl_xor_sync(0xffffffffu, mx, 2));
            const float mn = fmaxf(mrow[hi], mx);
            const float alpha = __expf(mrow[hi] - mn);
            mrow[hi] = mn;
            float rs = 0.f;
#pragma unroll
            for (int ni = 0; ni < 8; ni++) {
#pragma unroll
                for (int cc = 0; cc < 2; cc++) {
                    const float p = __expf(s[ni][2*hi+cc] - mn);
                    s[ni][2*hi+cc] = p;
                    rs += p;
                }
            }
            rs += __shfl_xor_sync(0xffffffffu, rs, 1);
            rs += __shfl_xor_sync(0xffffffffu, rs, 2);
            lrow[hi] = lrow[hi]*alpha + rs;
#pragma unroll
            for (int ni = 0; ni < 8; ni++) {
                o[ni][2*hi+0] *= alpha;
                o[ni][2*hi+1] *= alpha;
            }
        }

        // ---- O += P @ V, shfl-free; V interleaved: B-frag = LDS.64.
        // A k-slot j = key 2j (j<4) / 2(j-4)+1 (j>=4); b0/b1 = keys 8kk+2tig,+1
        // = vil row 4kk+tig, cols 2*(8ni+g), 2*(8ni+g)+1. ----
#pragma unroll
        for (int kk = 0; kk < 8; kk++) {
            uint32_t b0[8], b1[8];
            const float* vp = Vs + (4*kk + tig)*VLD2 + 2*g;
#pragma unroll
            for (int ni = 0; ni < 8; ni++) {
                const float2 vb = *(const float2*)(vp + 16*ni);
                b0[ni] = __float_as_uint(vb.x);
                b1[ni] = __float_as_uint(vb.y);
            }
            const uint32_t pa0 = f2tf32(s[kk][0]);
            const uint32_t pa1 = f2tf32(s[kk][2]);
            const uint32_t pa2 = f2tf32(s[kk][1]);
            const uint32_t pa3 = f2tf32(s[kk][3]);
#pragma unroll
            for (int ni = 0; ni < 8; ni++)
                mma_tf32(o[ni][0], o[ni][1], o[ni][2], o[ni][3],
                         pa0, pa1, pa2, pa3, b0[ni], b1[ni]);
        }
    }

    // ---- normalize + write ctx [b, s, h, hd] (tf32-rounded for out-proj) ----
#pragma unroll
    for (int hi = 0; hi < 2; hi++) {
        const float inv = 1.f / lrow[hi];
        const int row = q0 + rb + g + 8*hi;
        float* dst = g_ctx + ((size_t)b * SS + row) * DD + h * HDD;
#pragma unroll
        for (int ni = 0; ni < 8; ni++) {
            *(float2*)(dst + 8*ni + 2*tig) =
                make_float2(rtf(o[ni][2*hi+0]*inv),
                            rtf(o[ni][2*hi+1]*inv));
        }
    }
}

// ---------------------------------------------------------------------------
extern "C" void kernel_launch(void* const* d_in, const int* in_sizes, int n_in,
                              void* d_out, int out_size)
{
    const float* x  = (const float*)d_in[0];
    const float* wq = (const float*)d_in[1];
    const float* wk = (const float*)d_in[2];
    const float* wv = (const float*)d_in[3];
    const float* wo = (const float*)d_in[4];
    const float* bo = (const float*)d_in[5];
    float* out = (float*)d_out;

    float *gqkv, *gctx, *gxr, *gwr;
    cudaGetSymbolAddress((void**)&gqkv, g_qkv);
    cudaGetSymbolAddress((void**)&gctx, g_ctx);
    cudaGetSymbolAddress((void**)&gxr,  g_xr);
    cudaGetSymbolAddress((void**)&gwr,  g_wr);

    const int gemm_smem = 2 * GNS * GSTG * (int)sizeof(float);  // 110592
    cudaFuncSetAttribute(gemm_tf32,
                         cudaFuncAttributeMaxDynamicSharedMemorySize, gemm_smem);
    const int attn_smem = (128*KLD + 2*64*KLD + 2*32*VLD2) * (int)sizeof(float); // 108544
    cudaFuncSetAttribute(attn_mma,
                         cudaFuncAttributeMaxDynamicSharedMemorySize, attn_smem);

    // pre-round x + all 4 weights to tf32 (rna), one fused launch
    const int nx4 = BB*SS*DD/4;
    round_all<<<dim3((nx4+255)/256, 5), 256>>>(
        (const float4*)x, (const float4*)wq, (const float4*)wk,
        (const float4*)wv, (const float4*)wo, (float4*)gxr, (float4*)gwr);

    dim3 gblock(256);

    // fused QKV projection: z selects weight + output slice/layout
    gemm_tf32<<<dim3(DD/128, (BB*SS)/128, 3), gblock, gemm_smem>>>(
        gxr, gwr, nullptr, gqkv, 1);

    attn_mma<<<dim3(SS/128, BB*HH), 256, attn_smem>>>();

    gemm_tf32<<<dim3(DD/128, (BB*SS)/128, 1), gblock, gemm_smem>>>(
        gctx, gwr + 3*DD*DD, bo, out, 0);
}

// round 8
// speedup vs baseline: 1.0955x; 1.0449x over previous
#include <cuda_runtime.h>
#include <cstdint>

#define BB 2
#define SS 4096
#define DD 768
#define HH 12
#define HDD 64

// Scratch (device globals: no allocations allowed in kernel_launch)
__device__ float g_qkv[3*BB*SS*DD];   // q | k(col-pair-permuted) | v(row-pair-interleaved)
__device__ float g_ctx[BB*SS*DD];
__device__ float g_xr[BB*SS*DD];      // tf32-rounded x
__device__ float g_wr[4*DD*DD];       // tf32-rounded wq,wk,wv,wo

__device__ __forceinline__ uint32_t f2tf32(float x) {
    uint32_t u;
    asm("cvt.rna.tf32.f32 %0, %1;" : "=r"(u) : "f"(x));
    return u;
}
__device__ __forceinline__ float rtf(float x) { return __uint_as_float(f2tf32(x)); }

__device__ __forceinline__ void mma_tf32(
    float& d0, float& d1, float& d2, float& d3,
    uint32_t a0, uint32_t a1, uint32_t a2, uint32_t a3,
    uint32_t b0, uint32_t b1)
{
    asm volatile(
        "mma.sync.aligned.m16n8k8.row.col.f32.tf32.tf32.f32 "
        "{%0,%1,%2,%3}, {%4,%5,%6,%7}, {%8,%9}, {%0,%1,%2,%3};\n"
        : "+f"(d0), "+f"(d1), "+f"(d2), "+f"(d3)
        : "r"(a0), "r"(a1), "r"(a2), "r"(a3), "r"(b0), "r"(b1));
}

__device__ __forceinline__ void cpa16(void* dst, const void* src) {
    uint32_t d = (uint32_t)__cvta_generic_to_shared(dst);
    asm volatile("cp.async.ca.shared.global [%0], [%1], 16;\n" :: "r"(d), "l"(src));
}
#define CP_COMMIT asm volatile("cp.async.commit_group;\n" ::: "memory")
#define CP_WAITN(n) asm volatile("cp.async.wait_group %0;\n" :: "n"(n) : "memory")
#define CP_WAIT0  CP_WAITN(0)

// ---------------------------------------------------------------------------
// fused tf32 rounding: blockIdx.y selects x / wq / wk / wv / wo
// ---------------------------------------------------------------------------
__global__ void round_all(const float4* __restrict__ x,
                          const float4* __restrict__ wq, const float4* __restrict__ wk,
                          const float4* __restrict__ wv, const float4* __restrict__ wo,
                          float4* __restrict__ xr, float4* __restrict__ wr)
{
    const int nx4 = BB*SS*DD/4, nw4 = DD*DD/4;
    const int z = blockIdx.y;
    const float4* src; float4* dst; int n4;
    if (z == 0) { src = x; dst = xr; n4 = nx4; }
    else {
        src = (z == 1) ? wq : (z == 2) ? wk : (z == 3) ? wv : wo;
        dst = wr + (size_t)(z-1) * nw4;
        n4 = nw4;
    }
    int i = blockIdx.x * blockDim.x + threadIdx.x;
    if (i < n4) {
        float4 v = src[i];
        dst[i] = make_float4(rtf(v.x), rtf(v.y), rtf(v.z), rtf(v.w));
    }
}

// ---------------------------------------------------------------------------
// tf32 GEMM: C[M,N] = A[M,K] @ W[N,K]^T (+bias). CTA 128x128, BK=32,
// 8 warps (2x4) of 64x32. 2-stage cp.async pipeline (R5-proven structure:
// wait0 -> sync -> prefetch(it+1) -> compute; one barrier per K-iter).
// mode==0: plain fp32 output + bias (out-proj).
// mode==1: fused QKV (blockIdx.z = 0/1/2 -> Q/K/V), outputs tf32-rounded.
//   Q: plain layout.  K: column-pair-permuted within 8-groups.
//   V: row-pair-interleaved vil[b][s/2][h][2*hd + (s&1)].
// ---------------------------------------------------------------------------
#define GLD 36
#define GSTG (128*GLD)

__global__ __launch_bounds__(256) void gemm_tf32(
    const float* __restrict__ A, const float* __restrict__ Wbase,
    const float* __restrict__ bias, float* __restrict__ Cbase,
    int mode)
{
    extern __shared__ float gsm[];
    float* As = gsm;                 // 2 stages x 128 x GLD
    float* Ws = gsm + 2*GSTG;

    const int K = DD, N = DD;
    const float* W = Wbase + (size_t)blockIdx.z * DD*DD;
    float* C = Cbase + (size_t)blockIdx.z * BB*SS*DD;

    const int tid  = threadIdx.x;
    const int lane = tid & 31;
    const int warp = tid >> 5;
    const int g = lane >> 2, tig = lane & 3;
    const int wm = warp & 1;
    const int wn = warp >> 1;
    const int bm = blockIdx.y * 128;
    const int bn = blockIdx.x * 128;

    float acc[4][4][4];
#pragma unroll
    for (int mi = 0; mi < 4; mi++)
#pragma unroll
        for (int ni = 0; ni < 4; ni++)
#pragma unroll
            for (int c = 0; c < 4; c++) acc[mi][ni][c] = 0.f;

    const int nk = K / 32;

    {
#pragma unroll
        for (int i = 0; i < 4; i++) {
            const int id = tid + 256*i;
            const int r = id >> 3;
            const int c = (id & 7) << 2;
            cpa16(&As[r*GLD + c], A + (size_t)(bm + r)*K + c);
            cpa16(&Ws[r*GLD + c], W + (size_t)(bn + r)*K + c);
        }
        CP_COMMIT;
    }

    for (int it = 0; it < nk; it++) {
        CP_WAIT0;
        __syncthreads();
        const int s = it & 1;
        if (it + 1 < nk) {
            const int k1 = (it + 1) * 32;
            float* Ad = As + (s^1)*GSTG;
            float* Wd = Ws + (s^1)*GSTG;
#pragma unroll
            for (int i = 0; i < 4; i++) {
                const int id = tid + 256*i;
                const int r = id >> 3;
                const int c = (id & 7) << 2;
                cpa16(&Ad[r*GLD + c], A + (size_t)(bm + r)*K + k1 + c);
                cpa16(&Wd[r*GLD + c], W + (size_t)(bn + r)*K + k1 + c);
            }
            CP_COMMIT;
        }
        const float* Ab = As + s*GSTG;
        const float* Wb = Ws + s*GSTG;
#pragma unroll
        for (int kk = 0; kk < 4; kk++) {
            uint32_t b0[4], b1[4];
#pragma unroll
            for (int ni = 0; ni < 4; ni++) {
                const float* wp = Wb + (32*wn + 8*ni + g)*GLD + 8*kk + tig;
                b0[ni] = __float_as_uint(wp[0]);
                b1[ni] = __float_as_uint(wp[4]);
            }
#pragma unroll
            for (int mi = 0; mi < 4; mi++) {
                const int rb = 64*wm + 16*mi;
                const float* ap0 = Ab + (rb + g)*GLD + 8*kk + tig;
                const float* ap1 = Ab + (rb + g + 8)*GLD + 8*kk + tig;
                const uint32_t a0 = __float_as_uint(ap0[0]);
                const uint32_t a1 = __float_as_uint(ap1[0]);
                const uint32_t a2 = __float_as_uint(ap0[4]);
                const uint32_t a3 = __float_as_uint(ap1[4]);
#pragma unroll
                for (int ni = 0; ni < 4; ni++)
                    mma_tf32(acc[mi][ni][0], acc[mi][ni][1],
                             acc[mi][ni][2], acc[mi][ni][3],
                             a0, a1, a2, a3, b0[ni], b1[ni]);
            }
        }
    }

    const int z = blockIdx.z;
#pragma unroll
    for (int ni = 0; ni < 4; ni++) {
        const int col = bn + 32*wn + 8*ni + 2*tig;
        float bx = 0.f, by = 0.f;
        if (mode == 0 && bias) { bx = bias[col]; by = bias[col+1]; }
#pragma unroll
        for (int mi = 0; mi < 4; mi++) {
            const int r0 = bm + 64*wm + 16*mi + g;
            float v0 = acc[mi][ni][0] + bx, v1 = acc[mi][ni][1] + by;
            float v2 = acc[mi][ni][2] + bx, v3 = acc[mi][ni][3] + by;
            if (mode == 0) {
                *(float2*)(C + (size_t)r0*N + col)     = make_float2(v0, v1);
                *(float2*)(C + (size_t)(r0+8)*N + col) = make_float2(v2, v3);
                continue;
            }
            v0 = rtf(v0); v1 = rtf(v1); v2 = rtf(v2); v3 = rtf(v3);
            if (z == 0) {                 // Q: plain
                *(float2*)(C + (size_t)r0*N + col)     = make_float2(v0, v1);
                *(float2*)(C + (size_t)(r0+8)*N + col) = make_float2(v2, v3);
            } else if (z == 1) {          // K: col-pair permuted within 8-group
                const int pc = (col & ~7) | ((col & 3) << 1) | ((col >> 2) & 1);
                C[(size_t)r0*N + pc]       = v0;   // perm(col)
                C[(size_t)r0*N + pc + 2]   = v1;   // perm(col+1) = pc+2
                C[(size_t)(r0+8)*N + pc]     = v2;
                C[(size_t)(r0+8)*N + pc + 2] = v3;
            } else {                      // V: row-pair interleaved
                const int h = col >> 6, hd = col & 63;
#pragma unroll
                for (int rr = 0; rr < 2; rr++) {
                    const int r = r0 + 8*rr;
                    const int b = r >> 12, sq = r & (SS-1);
                    float* vp = C + ((size_t)(b*(SS/2) + (sq>>1))*HH + h)*128
                                  + 2*hd + (sq & 1);
                    vp[0] = rr ? v2 : v0;
                    vp[2] = rr ? v3 : v1;
                }
            }
        }
    }
}

// ---------------------------------------------------------------------------
// Flash attention, tf32 mma.sync (unchanged from R7).
// 8 warps (16-row bands), BQ=128, BK=64; K/V double-buffered cp.async.
// K col-pair-permuted -> S B-frag = LDS.64; V row-pair-interleaved -> PV
// B-frag = LDS.64, shfl-free. Q frags hoisted, pre-scaled by 1/8.
// ---------------------------------------------------------------------------
#define KLD 72
#define VLD2 136

__global__ __launch_bounds__(256, 2) void attn_mma()
{
    extern __shared__ float smm[];
    float* Qs  = smm;                        // 128 x KLD
    float* Ksb = smm + 128*KLD;              // 2 x 64 x KLD
    float* Vsb = Ksb + 2*64*KLD;             // 2 x 32 x VLD2

    const int tid  = threadIdx.x;
    const int lane = tid & 31;
    const int warp = tid >> 5;               // 0..7 -> 16-row band
    const int g = lane >> 2, tig = lane & 3;
    const int bh = blockIdx.y;
    const int b  = bh / HH;
    const int h  = bh % HH;
    const int qt = (gridDim.x - 1) - blockIdx.x;   // heavy tiles first
    const int q0 = qt * 128;

    const float* Qg = g_qkv + 0*BB*SS*DD + ((size_t)b * SS) * DD + h * HDD;
    const float* Kg = g_qkv + 1*BB*SS*DD + ((size_t)b * SS) * DD + h * HDD;
    // V interleaved: row p (key pair) at  vbase + p*(HH*128) + h*128
    const float* Vg = g_qkv + 2*BB*SS*DD + (size_t)b*(SS/2)*HH*128 + h*128;

    // prologue: Q tile + K/V tile 0
    {
#pragma unroll
        for (int i = 0; i < 8; i++) {             // Q: 128 rows x 16 chunks
            const int id = tid + 256*i;
            const int r = id >> 4;
            const int c = (id & 15) << 2;
            cpa16(&Qs[r*KLD + c], Qg + (size_t)(q0 + r)*DD + c);
        }
#pragma unroll
        for (int i = 0; i < 4; i++) {             // K: 64 rows x 16 chunks
            const int id = tid + 256*i;
            const int r = id >> 4;
            const int c = (id & 15) << 2;
            cpa16(&Ksb[r*KLD + c], Kg + (size_t)r*DD + c);
        }
#pragma unroll
        for (int i = 0; i < 4; i++) {             // V: 32 pair-rows x 32 chunks
            const int id = tid + 256*i;
            const int p = id >> 5;
            const int c = (id & 31) << 2;
            cpa16(&Vsb[p*VLD2 + c], Vg + (size_t)p*(HH*128) + c);
        }
        CP_COMMIT;
    }

    float qa[8][4];                 // hoisted Q fragments (pre-scaled by 1/8)
    float s[8][4], o[8][4], mrow[2], lrow[2];
#pragma unroll
    for (int hi = 0; hi < 2; hi++) { mrow[hi] = -1e30f; lrow[hi] = 0.f; }
#pragma unroll
    for (int ni = 0; ni < 8; ni++)
#pragma unroll
        for (int c = 0; c < 4; c++) o[ni][c] = 0.f;

    const int rb = 16*warp;

    const int nkt = 2*qt + 2;
    for (int kt = 0; kt < nkt; kt++) {
        CP_WAIT0;
        __syncthreads();
        const int st = kt & 1;
        if (kt + 1 < nkt) {                      // prefetch next K/V tile
            const int k1 = (kt + 1) * 64;
            float* Kd = Ksb + (st^1)*64*KLD;
            float* Vd = Vsb + (st^1)*32*VLD2;
#pragma unroll
            for (int i = 0; i < 4; i++) {
                const int id = tid + 256*i;
                const int r = id >> 4;
                const int c = (id & 15) << 2;
                cpa16(&Kd[r*KLD + c], Kg + (size_t)(k1 + r)*DD + c);
            }
#pragma unroll
            for (int i = 0; i < 4; i++) {
                const int id = tid + 256*i;
                const int p = id >> 5;
                const int c = (id & 31) << 2;
                cpa16(&Vd[p*VLD2 + c], Vg + (size_t)(k1/2 + p)*(HH*128) + c);
            }
            CP_COMMIT;
        }
        if (kt == 0) {                           // hoist Q frags once
#pragma unroll
            for (int kk = 0; kk < 8; kk++) {
                qa[kk][0] = 0.125f * Qs[(rb + g)*KLD     + 8*kk + tig];
                qa[kk][1] = 0.125f * Qs[(rb + g + 8)*KLD + 8*kk + tig];
                qa[kk][2] = 0.125f * Qs[(rb + g)*KLD     + 8*kk + tig + 4];
                qa[kk][3] = 0.125f * Qs[(rb + g + 8)*KLD + 8*kk + tig + 4];
            }
        }
        const float* Ks = Ksb + st*64*KLD;
        const float* Vs = Vsb + st*32*VLD2;
        const int k0 = kt * 64;

        // ---- S = (Q/8) @ K^T; K col-pair-permuted: B-frag = LDS.64 ----
#pragma unroll
        for (int ni = 0; ni < 8; ni++)
#pragma unroll
            for (int c = 0; c < 4; c++) s[ni][c] = 0.f;

#pragma unroll
        for (int kk = 0; kk < 8; kk++) {
            uint32_t b0[8], b1[8];
#pragma unroll
            for (int ni = 0; ni < 8; ni++) {
                const float2 kb = *(const float2*)(Ks + (8*ni + g)*KLD + 8*kk + 2*tig);
                b0[ni] = __float_as_uint(kb.x);   // logical col 8kk+tig
                b1[ni] = __float_as_uint(kb.y);   // logical col 8kk+tig+4
            }
            const uint32_t a0 = __float_as_uint(qa[kk][0]);
            const uint32_t a1 = __float_as_uint(qa[kk][1]);
            const uint32_t a2 = __float_as_uint(qa[kk][2]);
            const uint32_t a3 = __float_as_uint(qa[kk][3]);
#pragma unroll
            for (int ni = 0; ni < 8; ni++)
                mma_tf32(s[ni][0], s[ni][1], s[ni][2], s[ni][3],
                         a0, a1, a2, a3, b0[ni], b1[ni]);
        }

        // ---- online softmax (scores pre-scaled; 4-lane groups = row) ----
        const bool need_mask = (k0 + 63 > q0);
#pragma unroll
        for (int hi = 0; hi < 2; hi++) {
            const int row = q0 + rb + g + 8*hi;
            float mx = -1e30f;
#pragma unroll
            for (int ni = 0; ni < 8; ni++) {
#pragma unroll
                for (int cc = 0; cc < 2; cc++) {
                    float v = s[ni][2*hi+cc];
                    if (need_mask && (k0 + 8*ni + 2*tig + cc > row)) v = -1e30f;
                    s[ni][2*hi+cc] = v;
                    mx = fmaxf(mx, v);
                }
            }
            mx = fmaxf(mx, __shfl_xor_sync(0xffffffffu, mx, 1));
            mx = fmaxf(mx, __shfl_xor_sync(0xffffffffu, mx, 2));
            const float mn = fmaxf(mrow[hi], mx);
            const float alpha = __expf(mrow[hi] - mn);
            mrow[hi] = mn;
            float rs = 0.f;
#pragma unroll
            for (int ni = 0; ni < 8; ni++) {
#pragma unroll
                for (int cc = 0; cc < 2; cc++) {
                    const float p = __expf(s[ni][2*hi+cc] - mn);
                    s[ni][2*hi+cc] = p;
                    rs += p;
                }
            }
            rs += __shfl_xor_sync(0xffffffffu, rs, 1);
            rs += __shfl_xor_sync(0xffffffffu, rs, 2);
            lrow[hi] = lrow[hi]*alpha + rs;
#pragma unroll
            for (int ni = 0; ni < 8; ni++) {
                o[ni][2*hi+0] *= alpha;
                o[ni][2*hi+1] *= alpha;
            }
        }

        // ---- O += P @ V, shfl-free; V interleaved: B-frag = LDS.64 ----
#pragma unroll
        for (int kk = 0; kk < 8; kk++) {
            uint32_t b0[8], b1[8];
            const float* vp = Vs + (4*kk + tig)*VLD2 + 2*g;
#pragma unroll
            for (int ni = 0; ni < 8; ni++) {
                const float2 vb = *(const float2*)(vp + 16*ni);
                b0[ni] = __float_as_uint(vb.x);
                b1[ni] = __float_as_uint(vb.y);
            }
            const uint32_t pa0 = f2tf32(s[kk][0]);
            const uint32_t pa1 = f2tf32(s[kk][2]);
            const uint32_t pa2 = f2tf32(s[kk][1]);
            const uint32_t pa3 = f2tf32(s[kk][3]);
#pragma unroll
            for (int ni = 0; ni < 8; ni++)
                mma_tf32(o[ni][0], o[ni][1], o[ni][2], o[ni][3],
                         pa0, pa1, pa2, pa3, b0[ni], b1[ni]);
        }
    }

    // ---- normalize + write ctx [b, s, h, hd] (tf32-rounded for out-proj) ----
#pragma unroll
    for (int hi = 0; hi < 2; hi++) {
        const float inv = 1.f / lrow[hi];
        const int row = q0 + rb + g + 8*hi;
        float* dst = g_ctx + ((size_t)b * SS + row) * DD + h * HDD;
#pragma unroll
        for (int ni = 0; ni < 8; ni++) {
            *(float2*)(dst + 8*ni + 2*tig) =
                make_float2(rtf(o[ni][2*hi+0]*inv),
                            rtf(o[ni][2*hi+1]*inv));
        }
    }
}

// ---------------------------------------------------------------------------
extern "C" void kernel_launch(void* const* d_in, const int* in_sizes, int n_in,
                              void* d_out, int out_size)
{
    const float* x  = (const float*)d_in[0];
    const float* wq = (const float*)d_in[1];
    const float* wk = (const float*)d_in[2];
    const float* wv = (const float*)d_in[3];
    const float* wo = (const float*)d_in[4];
    const float* bo = (const float*)d_in[5];
    float* out = (float*)d_out;

    float *gqkv, *gctx, *gxr, *gwr;
    cudaGetSymbolAddress((void**)&gqkv, g_qkv);
    cudaGetSymbolAddress((void**)&gctx, g_ctx);
    cudaGetSymbolAddress((void**)&gxr,  g_xr);
    cudaGetSymbolAddress((void**)&gwr,  g_wr);

    const int gemm_smem = 4 * GSTG * (int)sizeof(float);        // 73728 (R5-proven)
    cudaFuncSetAttribute(gemm_tf32,
                         cudaFuncAttributeMaxDynamicSharedMemorySize, gemm_smem);
    const int attn_smem = (128*KLD + 2*64*KLD + 2*32*VLD2) * (int)sizeof(float); // 108544
    cudaFuncSetAttribute(attn_mma,
                         cudaFuncAttributeMaxDynamicSharedMemorySize, attn_smem);

    // pre-round x + all 4 weights to tf32 (rna), one fused launch
    const int nx4 = BB*SS*DD/4;
    round_all<<<dim3((nx4+255)/256, 5), 256>>>(
        (const float4*)x, (const float4*)wq, (const float4*)wk,
        (const float4*)wv, (const float4*)wo, (float4*)gxr, (float4*)gwr);

    dim3 gblock(256);

    // fused QKV projection: z selects weight + output slice/layout
    gemm_tf32<<<dim3(DD/128, (BB*SS)/128, 3), gblock, gemm_smem>>>(
        gxr, gwr, nullptr, gqkv, 1);

    attn_mma<<<dim3(SS/128, BB*HH), 256, attn_smem>>>();

    gemm_tf32<<<dim3(DD/128, (BB*SS)/128, 1), gblock, gemm_smem>>>(
        gctx, gwr + 3*DD*DD, bo, out, 0);
}

// round 9
// speedup vs baseline: 1.9136x; 1.7468x over previous
#include <cuda_runtime.h>
#include <cuda_fp16.h>
#include <cstdint>

#define BB 2
#define SS 4096
#define DD 768
#define HH 12
#define HDD 64

// Scratch (device globals: no allocations allowed in kernel_launch)
__device__ __half g_qkvh[3*BB*SS*DD];  // q(x0.125) | k | v(row-pair-interleaved)
__device__ __half g_ctxh[BB*SS*DD];    // attn output, fp16
__device__ __half g_xh[BB*SS*DD];      // fp16 x
__device__ __half g_wh[4*DD*DD];       // fp16 wq,wk,wv,wo

__device__ __forceinline__ uint32_t packh2(float lo, float hi) {
    __half2 h = __floats2half2_rn(lo, hi);
    return *reinterpret_cast<uint32_t*>(&h);
}

__device__ __forceinline__ void mma_f16(
    float& d0, float& d1, float& d2, float& d3,
    uint32_t a0, uint32_t a1, uint32_t a2, uint32_t a3,
    uint32_t b0, uint32_t b1)
{
    asm volatile(
        "mma.sync.aligned.m16n8k16.row.col.f32.f16.f16.f32 "
        "{%0,%1,%2,%3}, {%4,%5,%6,%7}, {%8,%9}, {%0,%1,%2,%3};\n"
        : "+f"(d0), "+f"(d1), "+f"(d2), "+f"(d3)
        : "r"(a0), "r"(a1), "r"(a2), "r"(a3), "r"(b0), "r"(b1));
}

__device__ __forceinline__ void cpa16(void* dst, const void* src) {
    uint32_t d = (uint32_t)__cvta_generic_to_shared(dst);
    asm volatile("cp.async.ca.shared.global [%0], [%1], 16;\n" :: "r"(d), "l"(src));
}
#define CP_COMMIT asm volatile("cp.async.commit_group;\n" ::: "memory")
#define CP_WAIT0  asm volatile("cp.async.wait_group 0;\n" ::: "memory")

// ---------------------------------------------------------------------------
// fused fp32 -> fp16 conversion: blockIdx.y selects x / wq / wk / wv / wo
// ---------------------------------------------------------------------------
__global__ void conv_half(const float4* __restrict__ x,
                          const float4* __restrict__ wq, const float4* __restrict__ wk,
                          const float4* __restrict__ wv, const float4* __restrict__ wo,
                          __half* __restrict__ xh, __half* __restrict__ wh)
{
    const int nx4 = BB*SS*DD/4, nw4 = DD*DD/4;
    const int z = blockIdx.y;
    const float4* src; __half* dst; int n4;
    if (z == 0) { src = x; dst = xh; n4 = nx4; }
    else {
        src = (z == 1) ? wq : (z == 2) ? wk : (z == 3) ? wv : wo;
        dst = wh + (size_t)(z-1) * DD*DD;
        n4 = nw4;
    }
    int i = blockIdx.x * blockDim.x + threadIdx.x;
    if (i < n4) {
        float4 v = src[i];
        __half2* d2 = (__half2*)(dst + 4*(size_t)i);
        d2[0] = __floats2half2_rn(v.x, v.y);
        d2[1] = __floats2half2_rn(v.z, v.w);
    }
}

// ---------------------------------------------------------------------------
// fp16 GEMM: C[M,N] = A[M,K] @ W[N,K]^T (+bias). CTA 128x128, BK=64,
// 8 warps (2x4) of 64x32, m16n8k16 fp16 mma with fp32 accumulation.
// 2-stage cp.async pipeline (R5/R8-proven loop structure).
// SMEM row stride 72 halves (36 words, ==4 mod 32): frag LDS.32 banks 4g+tig.
// mode==0: fp32 out + bias (out-proj, A = g_ctxh).
// mode==1: fused QKV via blockIdx.z: Q (x0.125) | K plain | V pair-interleave.
// ---------------------------------------------------------------------------
#define GLH 72
#define GSTGH (128*GLH)

__global__ __launch_bounds__(256) void gemm_f16(
    const __half* __restrict__ A, const __half* __restrict__ Wbase,
    const float* __restrict__ bias, float* __restrict__ Cf,
    __half* __restrict__ Ch, int mode)
{
    extern __shared__ __half hsm[];
    __half* As = hsm;                 // 2 stages x 128 x GLH
    __half* Ws = hsm + 2*GSTGH;

    const int K = DD, N = DD;
    const __half* W = Wbase + (size_t)blockIdx.z * DD*DD;

    const int tid  = threadIdx.x;
    const int lane = tid & 31;
    const int warp = tid >> 5;
    const int g = lane >> 2, tig = lane & 3;
    const int wm = warp & 1;
    const int wn = warp >> 1;
    const int bm = blockIdx.y * 128;
    const int bn = blockIdx.x * 128;

    float acc[4][4][4];
#pragma unroll
    for (int mi = 0; mi < 4; mi++)
#pragma unroll
        for (int ni = 0; ni < 4; ni++)
#pragma unroll
            for (int c = 0; c < 4; c++) acc[mi][ni][c] = 0.f;

    const int nk = K / 64;            // 12

    {
#pragma unroll
        for (int i = 0; i < 8; i++) {
            const int id = tid + 256*i;
            if (id < 1024) {          // A: 128 rows x 8 chunks of 8 halves
                const int r = id >> 3, c = id & 7;
                cpa16(&As[r*GLH + c*8], A + (size_t)(bm + r)*K + c*8);
            } else {
                const int id2 = id - 1024, r = id2 >> 3, c = id2 & 7;
                cpa16(&Ws[r*GLH + c*8], W + (size_t)(bn + r)*K + c*8);
            }
        }
        CP_COMMIT;
    }

    for (int it = 0; it < nk; it++) {
        CP_WAIT0;
        __syncthreads();
        const int s = it & 1;
        if (it + 1 < nk) {
            const int k1 = (it + 1) * 64;
            __half* Ad = As + (s^1)*GSTGH;
            __half* Wd = Ws + (s^1)*GSTGH;
#pragma unroll
            for (int i = 0; i < 8; i++) {
                const int id = tid + 256*i;
                if (id < 1024) {
                    const int r = id >> 3, c = id & 7;
                    cpa16(&Ad[r*GLH + c*8], A + (size_t)(bm + r)*K + k1 + c*8);
                } else {
                    const int id2 = id - 1024, r = id2 >> 3, c = id2 & 7;
                    cpa16(&Wd[r*GLH + c*8], W + (size_t)(bn + r)*K + k1 + c*8);
                }
            }
            CP_COMMIT;
        }
        const uint32_t* Ab = (const uint32_t*)(As + s*GSTGH);
        const uint32_t* Wb = (const uint32_t*)(Ws + s*GSTGH);
#pragma unroll
        for (int kk = 0; kk < 4; kk++) {     // 4 k-chunks of 16
            uint32_t b0[4], b1[4];
#pragma unroll
            for (int ni = 0; ni < 4; ni++) {
                const uint32_t* wp = Wb + (32*wn + 8*ni + g)*36 + 8*kk + tig;
                b0[ni] = wp[0];              // W[col][16kk+2tig .. +1]
                b1[ni] = wp[4];              // W[col][16kk+8+2tig .. +1]
            }
#pragma unroll
            for (int mi = 0; mi < 4; mi++) {
                const int rb = 64*wm + 16*mi;
                const uint32_t* ap0 = Ab + (rb + g)*36 + 8*kk + tig;
                const uint32_t* ap1 = Ab + (rb + g + 8)*36 + 8*kk + tig;
                const uint32_t a0 = ap0[0];
                const uint32_t a1 = ap1[0];
                const uint32_t a2 = ap0[4];
                const uint32_t a3 = ap1[4];
#pragma unroll
                for (int ni = 0; ni < 4; ni++)
                    mma_f16(acc[mi][ni][0], acc[mi][ni][1],
                            acc[mi][ni][2], acc[mi][ni][3],
                            a0, a1, a2, a3, b0[ni], b1[ni]);
            }
        }
    }

    const int z = blockIdx.z;
#pragma unroll
    for (int ni = 0; ni < 4; ni++) {
        const int col = bn + 32*wn + 8*ni + 2*tig;
        float bx = 0.f, by = 0.f;
        if (mode == 0 && bias) { bx = bias[col]; by = bias[col+1]; }
#pragma unroll
        for (int mi = 0; mi < 4; mi++) {
            const int r0 = bm + 64*wm + 16*mi + g;
            float v0 = acc[mi][ni][0] + bx, v1 = acc[mi][ni][1] + by;
            float v2 = acc[mi][ni][2] + bx, v3 = acc[mi][ni][3] + by;
            if (mode == 0) {
                *(float2*)(Cf + (size_t)r0*N + col)     = make_float2(v0, v1);
                *(float2*)(Cf + (size_t)(r0+8)*N + col) = make_float2(v2, v3);
                continue;
            }
            __half* C = Ch + (size_t)z * BB*SS*DD;
            if (z == 0) {                 // Q, pre-scaled by 1/8 (exact)
                v0 *= 0.125f; v1 *= 0.125f; v2 *= 0.125f; v3 *= 0.125f;
            }
            if (z <= 1) {                 // Q/K: plain [s][768] fp16
                *(__half2*)(C + (size_t)r0*N + col) = __floats2half2_rn(v0, v1);
                *(__half2*)(C + (size_t)(r0+8)*N + col) = __floats2half2_rn(v2, v3);
            } else {                      // V: row-pair interleaved halves
                const int h = col >> 6, hd = col & 63;
#pragma unroll
                for (int rr = 0; rr < 2; rr++) {
                    const int r = r0 + 8*rr;
                    const int b = r >> 12, sq = r & (SS-1);
                    __half* vp = C + ((size_t)(b*(SS/2) + (sq>>1))*HH + h)*128
                                   + 2*hd + (sq & 1);
                    vp[0] = __float2half_rn(rr ? v2 : v0);
                    vp[2] = __float2half_rn(rr ? v3 : v1);
                }
            }
        }
    }
}

// ---------------------------------------------------------------------------
// Flash attention, fp16 m16n8k16 mma, fp32 accum + softmax.
// 8 warps (16-row bands), BQ=128, BK=64; K/V double-buffered cp.async.
// Q pre-scaled 1/8 in gmem; frags are natural half2 loads (no permutes).
// PV A-frag = packh2 of S registers (no shfl). V pair-interleaved.
// Strides: Q/K 72 halves (36 wd, banks 4g+tig), V 144 halves (72 wd, 8tig+g).
// ---------------------------------------------------------------------------
#define KLH 72
#define VLH 144

__global__ __launch_bounds__(256, 2) void attn_f16()
{
    extern __shared__ __half hsmm[];
    __half* Qs  = hsmm;                       // 128 x KLH
    __half* Ksb = hsmm + 128*KLH;             // 2 x 64 x KLH
    __half* Vsb = Ksb + 2*64*KLH;             // 2 x 32 x VLH

    const int tid  = threadIdx.x;
    const int lane = tid & 31;
    const int warp = tid >> 5;                // 0..7 -> 16-row band
    const int g = lane >> 2, tig = lane & 3;
    const int bh = blockIdx.y;
    const int b  = bh / HH;
    const int h  = bh % HH;
    const int qt = (gridDim.x - 1) - blockIdx.x;   // heavy tiles first
    const int q0 = qt * 128;

    const __half* Qg = g_qkvh + 0*BB*SS*DD + ((size_t)b * SS) * DD + h * HDD;
    const __half* Kg = g_qkvh + 1*BB*SS*DD + ((size_t)b * SS) * DD + h * HDD;
    const __half* Vg = g_qkvh + 2*BB*SS*DD + (size_t)b*(SS/2)*HH*128 + h*128;

    // prologue: Q tile + K/V tile 0
    {
#pragma unroll
        for (int i = 0; i < 4; i++) {             // Q: 128 rows x 8 chunks
            const int id = tid + 256*i;
            const int r = id >> 3, c = id & 7;
            cpa16(&Qs[r*KLH + c*8], Qg + (size_t)(q0 + r)*DD + c*8);
        }
#pragma unroll
        for (int i = 0; i < 2; i++) {             // K: 64 rows x 8 chunks
            const int id = tid + 256*i;
            const int r = id >> 3, c = id & 7;
            cpa16(&Ksb[r*KLH + c*8], Kg + (size_t)r*DD + c*8);
        }
#pragma unroll
        for (int i = 0; i < 2; i++) {             // V: 32 pair-rows x 16 chunks
            const int id = tid + 256*i;
            const int p = id >> 4, c = id & 15;
            cpa16(&Vsb[p*VLH + c*8], Vg + (size_t)p*(HH*128) + c*8);
        }
        CP_COMMIT;
    }

    uint32_t qa[4][4];              // hoisted Q fragments (half2, pre-scaled)
    float s[8][4], o[8][4], mrow[2], lrow[2];
#pragma unroll
    for (int hi = 0; hi < 2; hi++) { mrow[hi] = -1e30f; lrow[hi] = 0.f; }
#pragma unroll
    for (int ni = 0; ni < 8; ni++)
#pragma unroll
        for (int c = 0; c < 4; c++) o[ni][c] = 0.f;

    const int rb = 16*warp;

    const int nkt = 2*qt + 2;
    for (int kt = 0; kt < nkt; kt++) {
        CP_WAIT0;
        __syncthreads();
        const int st = kt & 1;
        if (kt + 1 < nkt) {                      // prefetch next K/V tile
            const int k1 = (kt + 1) * 64;
            __half* Kd = Ksb + (st^1)*64*KLH;
            __half* Vd = Vsb + (st^1)*32*VLH;
#pragma unroll
            for (int i = 0; i < 2; i++) {
                const int id = tid + 256*i;
                const int r = id >> 3, c = id & 7;
                cpa16(&Kd[r*KLH + c*8], Kg + (size_t)(k1 + r)*DD + c*8);
            }
#pragma unroll
            for (int i = 0; i < 2; i++) {
                const int id = tid + 256*i;
                const int p = id >> 4, c = id & 15;
                cpa16(&Vd[p*VLH + c*8], Vg + (size_t)(k1/2 + p)*(HH*128) + c*8);
            }
            CP_COMMIT;
        }
        if (kt == 0) {                           // hoist Q frags once
            const uint32_t* Q32 = (const uint32_t*)Qs;
#pragma unroll
            for (int kk = 0; kk < 4; kk++) {
                const uint32_t* qp0 = Q32 + (rb + g)*36 + 8*kk + tig;
                const uint32_t* qp1 = Q32 + (rb + g + 8)*36 + 8*kk + tig;
                qa[kk][0] = qp0[0];
                qa[kk][1] = qp1[0];
                qa[kk][2] = qp0[4];
                qa[kk][3] = qp1[4];
            }
        }
        const uint32_t* Ks32 = (const uint32_t*)(Ksb + st*64*KLH);
        const uint32_t* Vs32 = (const uint32_t*)(Vsb + st*32*VLH);
        const int k0 = kt * 64;

        // ---- S = (Q/8) @ K^T (16 x 64 per warp, 4 k-chunks of 16) ----
#pragma unroll
        for (int ni = 0; ni < 8; ni++)
#pragma unroll
            for (int c = 0; c < 4; c++) s[ni][c] = 0.f;

#pragma unroll
        for (int kk = 0; kk < 4; kk++) {
            uint32_t b0[8], b1[8];
#pragma unroll
            for (int ni = 0; ni < 8; ni++) {
                const uint32_t* kp = Ks32 + (8*ni + g)*36 + 8*kk + tig;
                b0[ni] = kp[0];
                b1[ni] = kp[4];
            }
#pragma unroll
            for (int ni = 0; ni < 8; ni++)
                mma_f16(s[ni][0], s[ni][1], s[ni][2], s[ni][3],
                        qa[kk][0], qa[kk][1], qa[kk][2], qa[kk][3],
                        b0[ni], b1[ni]);
        }

        // ---- online softmax (scores pre-scaled; 4-lane groups = row) ----
        const bool need_mask = (k0 + 63 > q0);
#pragma unroll
        for (int hi = 0; hi < 2; hi++) {
            const int row = q0 + rb + g + 8*hi;
            float mx = -1e30f;
#pragma unroll
            for (int ni = 0; ni < 8; ni++) {
#pragma unroll
                for (int cc = 0; cc < 2; cc++) {
                    float v = s[ni][2*hi+cc];
                    if (need_mask && (k0 + 8*ni + 2*tig + cc > row)) v = -1e30f;
                    s[ni][2*hi+cc] = v;
                    mx = fmaxf(mx, v);
                }
            }
            mx = fmaxf(mx, __shfl_xor_sync(0xffffffffu, mx, 1));
            mx = fmaxf(mx, __shfl_xor_sync(0xffffffffu, mx, 2));
            const float mn = fmaxf(mrow[hi], mx);
            const float alpha = __expf(mrow[hi] - mn);
            mrow[hi] = mn;
            float rs = 0.f;
#pragma unroll
            for (int ni = 0; ni < 8; ni++) {
#pragma unroll
                for (int cc = 0; cc < 2; cc++) {
                    const float p = __expf(s[ni][2*hi+cc] - mn);
                    s[ni][2*hi+cc] = p;
                    rs += p;
                }
            }
            rs += __shfl_xor_sync(0xffffffffu, rs, 1);
            rs += __shfl_xor_sync(0xffffffffu, rs, 2);
            lrow[hi] = lrow[hi]*alpha + rs;
#pragma unroll
            for (int ni = 0; ni < 8; ni++) {
                o[ni][2*hi+0] *= alpha;
                o[ni][2*hi+1] *= alpha;
            }
        }

        // ---- O += P @ V; A-frag packed from S regs, B-frag = half2 LDS ----
#pragma unroll
        for (int kk = 0; kk < 4; kk++) {
            uint32_t b0[8], b1[8];
#pragma unroll
            for (int ni = 0; ni < 8; ni++) {
                b0[ni] = Vs32[(8*kk + tig)*72 + 8*ni + g];       // keys 16kk+2tig,+1
                b1[ni] = Vs32[(8*kk + 4 + tig)*72 + 8*ni + g];   // keys +8
            }
            const uint32_t pa0 = packh2(s[2*kk][0],   s[2*kk][1]);
            const uint32_t pa1 = packh2(s[2*kk][2],   s[2*kk][3]);
            const uint32_t pa2 = packh2(s[2*kk+1][0], s[2*kk+1][1]);
            const uint32_t pa3 = packh2(s[2*kk+1][2], s[2*kk+1][3]);
#pragma unroll
            for (int ni = 0; ni < 8; ni++)
                mma_f16(o[ni][0], o[ni][1], o[ni][2], o[ni][3],
                        pa0, pa1, pa2, pa3, b0[ni], b1[ni]);
        }
    }

    // ---- normalize + write ctx [b, s, h*64+hd] fp16 ----
#pragma unroll
    for (int hi = 0; hi < 2; hi++) {
        const float inv = 1.f / lrow[hi];
        const int row = q0 + rb + g + 8*hi;
        __half* dst = g_ctxh + ((size_t)b * SS + row) * DD + h * HDD;
#pragma unroll
        for (int ni = 0; ni < 8; ni++) {
            *(__half2*)(dst + 8*ni + 2*tig) =
                __floats2half2_rn(o[ni][2*hi+0]*inv, o[ni][2*hi+1]*inv);
        }
    }
}

// ---------------------------------------------------------------------------
extern "C" void kernel_launch(void* const* d_in, const int* in_sizes, int n_in,
                              void* d_out, int out_size)
{
    const float* x  = (const float*)d_in[0];
    const float* wq = (const float*)d_in[1];
    const float* wk = (const float*)d_in[2];
    const float* wv = (const float*)d_in[3];
    const float* wo = (const float*)d_in[4];
    const float* bo = (const float*)d_in[5];
    float* out = (float*)d_out;

    __half *gqkvh, *gctxh, *gxh, *gwh;
    cudaGetSymbolAddress((void**)&gqkvh, g_qkvh);
    cudaGetSymbolAddress((void**)&gctxh, g_ctxh);
    cudaGetSymbolAddress((void**)&gxh,   g_xh);
    cudaGetSymbolAddress((void**)&gwh,   g_wh);

    const int gemm_smem = 4 * GSTGH * (int)sizeof(__half);      // 73728
    cudaFuncSetAttribute(gemm_f16,
                         cudaFuncAttributeMaxDynamicSharedMemorySize, gemm_smem);
    const int attn_smem = (128*KLH + 2*64*KLH + 2*32*VLH) * (int)sizeof(__half); // 55296
    cudaFuncSetAttribute(attn_f16,
                         cudaFuncAttributeMaxDynamicSharedMemorySize, attn_smem);

    // convert x + all 4 weights to fp16, one fused launch
    const int nx4 = BB*SS*DD/4;
    conv_half<<<dim3((nx4+255)/256, 5), 256>>>(
        (const float4*)x, (const float4*)wq, (const float4*)wk,
        (const float4*)wv, (const float4*)wo, gxh, gwh);

    dim3 gblock(256);

    // fused QKV projection: z selects weight + output slice/layout
    gemm_f16<<<dim3(DD/128, (BB*SS)/128, 3), gblock, gemm_smem>>>(
        gxh, gwh, nullptr, nullptr, gqkvh, 1);

    attn_f16<<<dim3(SS/128, BB*HH), 256, attn_smem>>>();

    gemm_f16<<<dim3(DD/128, (BB*SS)/128, 1), gblock, gemm_smem>>>(
        gctxh, gwh + 3*(size_t)DD*DD, bo, out, nullptr, 0);
}